// round 7
// baseline (speedup 1.0000x reference)
#include <cuda_runtime.h>
#include <cuda_bf16.h>

#define D 128
#define MAXN 50176    // padded N
#define MAXE 524288

// ---------------- scratch (device globals, no allocation) ----------------
__device__ float g_x[MAXN * D];     // embedding (layer-0 input)
__device__ float g_h[MAXN * D];     // pre-BN activations (layer output)
__device__ float g_agg[MAXN * D];
__device__ float g_onorm[MAXN];
__device__ float g_inorm[MAXN];
__device__ float g_colsum[D];
__device__ float g_colsq[D];
__device__ float g_scale[D];        // BN scale of PREVIOUS layer (init 1)
__device__ float g_shift[D];        // BN shift of PREVIOUS layer (init 0)

// CSR structures
__device__ int   g_outdeg[MAXN];
__device__ int   g_indeg[MAXN];
__device__ int   g_rowptr[MAXN + 1];
__device__ int   g_cursor[MAXN];
__device__ int   g_chunksum[256];
__device__ int   g_chunkoff[256];
__device__ int2  g_epack[MAXE];     // (src, onorm-bits)

// ---------------- f32x2 helpers ----------------
__device__ __forceinline__ unsigned long long pack2(float x, float y) {
    unsigned long long r;
    asm("mov.b64 %0, {%1, %2};" : "=l"(r) : "f"(x), "f"(y));
    return r;
}
__device__ __forceinline__ void ffma2(unsigned long long& d,
                                      unsigned long long a,
                                      unsigned long long b) {
    asm("fma.rn.f32x2 %0, %1, %2, %0;" : "+l"(d) : "l"(a), "l"(b));
}
__device__ __forceinline__ float2 unpack2(unsigned long long v) {
    float2 r;
    asm("mov.b64 {%0, %1}, %2;" : "=f"(r.x), "=f"(r.y) : "l"(v));
    return r;
}

// ---------------- prep: zero degrees + identity BN ----------------
__global__ void prep_kernel(int N) {
    int i = blockIdx.x * blockDim.x + threadIdx.x;
    if (i < N) { g_outdeg[i] = 0; g_indeg[i] = 0; }
    if (i < D) { g_scale[i] = 1.0f; g_shift[i] = 0.0f; }
}

__global__ void deg_kernel(const int* __restrict__ src,
                           const int* __restrict__ dst, int E) {
    int e = blockIdx.x * blockDim.x + threadIdx.x;
    if (e < E) {
        atomicAdd(&g_outdeg[src[e]], 1);
        atomicAdd(&g_indeg[dst[e]], 1);
    }
}

// ---------------- scan of indeg -> rowptr; also finalize norms ----------
__global__ void scan1_kernel(int N) {
    __shared__ int sd[256];
    int i = blockIdx.x * 256 + threadIdx.x;
    int dv = (i < N) ? g_indeg[i] : 0;
    sd[threadIdx.x] = dv;
    if (i < N) {
        int a = g_outdeg[i];
        g_onorm[i] = (a > 0) ? rsqrtf((float)a) : 0.f;
        g_inorm[i] = (dv > 0) ? rsqrtf((float)dv) : 0.f;
    }
    __syncthreads();
    for (int s = 128; s > 0; s >>= 1) {
        if (threadIdx.x < s) sd[threadIdx.x] += sd[threadIdx.x + s];
        __syncthreads();
    }
    if (threadIdx.x == 0) g_chunksum[blockIdx.x] = sd[0];
}

__global__ void scan2_kernel(int nch) {
    __shared__ int sd[256];
    int t = threadIdx.x;
    int v = (t < nch) ? g_chunksum[t] : 0;
    sd[t] = v;
    __syncthreads();
    for (int off = 1; off < 256; off <<= 1) {
        int val = (t >= off) ? sd[t - off] : 0;
        __syncthreads();
        sd[t] += val;
        __syncthreads();
    }
    if (t < nch) g_chunkoff[t] = sd[t] - v;  // exclusive
}

__global__ void scan3_kernel(int N, int E) {
    __shared__ int sd[256];
    int t = threadIdx.x;
    int i = blockIdx.x * 256 + t;
    int v = (i < N) ? g_indeg[i] : 0;
    sd[t] = v;
    __syncthreads();
    for (int off = 1; off < 256; off <<= 1) {
        int val = (t >= off) ? sd[t - off] : 0;
        __syncthreads();
        sd[t] += val;
        __syncthreads();
    }
    if (i < N) {
        int rp = g_chunkoff[blockIdx.x] + sd[t] - v;
        g_rowptr[i] = rp;
        g_cursor[i] = rp;
    }
    if (i == 0) g_rowptr[N] = E;
}

__global__ void fill_kernel(const int* __restrict__ src,
                            const int* __restrict__ dst, int E) {
    int e = blockIdx.x * blockDim.x + threadIdx.x;
    if (e < E) {
        int s = src[e];
        int d = dst[e];
        int p = atomicAdd(&g_cursor[d], 1);
        g_epack[p] = make_int2(s, __float_as_int(g_onorm[s]));
    }
}

// ---------------- embedding gather ----------------
__global__ void gather_kernel(const int* __restrict__ node_ids,
                              const float* __restrict__ emb, int N) {
    int gid = blockIdx.x * blockDim.x + threadIdx.x;
    if (gid < N * 32) {
        int i = gid >> 5;
        int c = gid & 31;
        ((float4*)g_x)[gid] = ((const float4*)emb)[node_ids[i] * 32 + c];
    }
}

// ---------------- CSR gather aggregation (BN fold), warp per dst --------
// input rows are raw h (or embedding x for layer 0); BN of prev layer is
// folded:  agg[d] = inorm[d] * ( scale .* sum(w_e*h[s]) + shift * sum(w_e) )
// Also zeroes this layer's BN stat accumulators.
__global__ void gather_agg_kernel(int use_h, int N) {
    int gid = blockIdx.x * blockDim.x + threadIdx.x;
    int w = gid >> 5;
    int lane = gid & 31;
    if (blockIdx.x == 0 && threadIdx.x < 128) {
        g_colsum[threadIdx.x] = 0.f;
        g_colsq[threadIdx.x] = 0.f;
    }
    if (w >= N) return;
    const float* buf = use_h ? g_h : g_x;
    int beg = g_rowptr[w];
    int end = g_rowptr[w + 1];
    float4 acc = make_float4(0.f, 0.f, 0.f, 0.f);
    float sw = 0.f;
#pragma unroll 8
    for (int j = beg; j < end; ++j) {
        int2 e = g_epack[j];
        float wt = __int_as_float(e.y);
        sw += wt;
        float4 v = ((const float4*)buf)[e.x * 32 + lane];
        acc.x += wt * v.x;
        acc.y += wt * v.y;
        acc.z += wt * v.z;
        acc.w += wt * v.w;
    }
    float inn = g_inorm[w];
    float4 sc = ((const float4*)g_scale)[lane];
    float4 sh = ((const float4*)g_shift)[lane];
    float4 o;
    o.x = inn * (sc.x * acc.x + sh.x * sw);
    o.y = inn * (sc.y * acc.y + sh.y * sw);
    o.z = inn * (sc.z * acc.z + sh.z * sw);
    o.w = inn * (sc.w * acc.w + sh.w * sw);
    ((float4*)g_agg)[w * 32 + lane] = o;
}

// ---------------- fused dual GEMM + bias + relu + residual + BN stats ----
// h = relu(agg @ W + b) + relu(normBN(buf) @ Rw + rb);  accumulates column
// sum / sumsq of h. 512 threads, 64 rows/block, 4x8 per-thread tiles.
#define AS_STRIDE 132
#define SMEM_FLOATS (32768 + 2 * 64 * AS_STRIDE + 256 + 1024)
#define SMEM_BYTES (SMEM_FLOATS * 4)

__global__ __launch_bounds__(512, 1)
void gemm_kernel(const float* __restrict__ W, const float* __restrict__ R,
                 const float* __restrict__ b, const float* __restrict__ rb,
                 int use_h, int N) {
    extern __shared__ float sm[];
    float* Wsm  = sm;                       // 16384
    float* Rsm  = sm + 16384;               // 16384
    float* As   = sm + 32768;               // 8448
    float* Xs   = As + 64 * AS_STRIDE;      // 8448
    float* bsm  = Xs + 64 * AS_STRIDE;      // 128
    float* rbsm = bsm + 128;                // 128
    float* scs4 = rbsm + 128;               // 512 (4 replicas x 128)
    float* scq4 = scs4 + 512;               // 512

    const int tid = threadIdx.x;
    const int rowbase = blockIdx.x * 64;
    const float* buf = use_h ? g_h : g_x;

    // weights + biases + zero stat replicas
    for (int idx = tid; idx < 4096; idx += 512) {
        ((float4*)Wsm)[idx] = ((const float4*)W)[idx];
        ((float4*)Rsm)[idx] = ((const float4*)R)[idx];
    }
    if (tid < 128) { bsm[tid] = b[tid]; rbsm[tid] = rb[tid]; }
    scs4[tid] = 0.f;
    scq4[tid] = 0.f;

    // input tiles: As = agg (pre-folded), Xs = BN(buf) on the fly
    for (int idx = tid; idx < 2048; idx += 512) {
        int r = idx >> 5;
        int c4 = idx & 31;
        int row = rowbase + r;
        float4 va = make_float4(0.f, 0.f, 0.f, 0.f);
        float4 vx = va;
        if (row < N) {
            va = ((const float4*)g_agg)[row * 32 + c4];
            float4 v = ((const float4*)buf)[row * 32 + c4];
            float4 sc = ((const float4*)g_scale)[c4];
            float4 sh = ((const float4*)g_shift)[c4];
            vx.x = v.x * sc.x + sh.x;
            vx.y = v.y * sc.y + sh.y;
            vx.z = v.z * sc.z + sh.z;
            vx.w = v.w * sc.w + sh.w;
        }
        *(float4*)(As + r * AS_STRIDE + c4 * 4) = va;
        *(float4*)(Xs + r * AS_STRIDE + c4 * 4) = vx;
    }
    __syncthreads();

    const int h = tid & 255;
    const bool first = (tid < 256);          // branch 0: agg@W
    const float* Mt = first ? As : Xs;
    const float* Wt = first ? Wsm : Rsm;
    const int cg = h & 15;                    // cols [cg*8, cg*8+8)
    const int rg = h >> 4;                    // rows [rg*4, rg*4+4)
    const float* mrow = Mt + rg * 4 * AS_STRIDE;
    const float* wcol = Wt + cg * 8;

    unsigned long long acc[4][4];
#pragma unroll
    for (int i = 0; i < 4; i++)
#pragma unroll
        for (int j = 0; j < 4; j++) acc[i][j] = 0ull;

#pragma unroll 2
    for (int k4 = 0; k4 < 32; ++k4) {
        float ar[4][4];
        *(float4*)ar[0] = *(const float4*)(mrow + 0 * AS_STRIDE + k4 * 4);
        *(float4*)ar[1] = *(const float4*)(mrow + 1 * AS_STRIDE + k4 * 4);
        *(float4*)ar[2] = *(const float4*)(mrow + 2 * AS_STRIDE + k4 * 4);
        *(float4*)ar[3] = *(const float4*)(mrow + 3 * AS_STRIDE + k4 * 4);
#pragma unroll
        for (int kk = 0; kk < 4; ++kk) {
            int k = k4 * 4 + kk;
            ulonglong2 wA = *(const ulonglong2*)(wcol + k * 128);
            ulonglong2 wB = *(const ulonglong2*)(wcol + k * 128 + 4);
#pragma unroll
            for (int i = 0; i < 4; i++) {
                unsigned long long ad = pack2(ar[i][kk], ar[i][kk]);
                ffma2(acc[i][0], ad, wA.x);
                ffma2(acc[i][1], ad, wA.y);
                ffma2(acc[i][2], ad, wB.x);
                ffma2(acc[i][3], ad, wB.y);
            }
        }
    }

    __syncthreads();
    float* Hs = As;  // reuse As region for relu(agg@W + b)
    if (first) {
#pragma unroll
        for (int i = 0; i < 4; i++) {
            int rl = rg * 4 + i;
#pragma unroll
            for (int j = 0; j < 4; j++) {
                float2 v = unpack2(acc[i][j]);
                int col = cg * 8 + 2 * j;
                v.x = fmaxf(v.x + bsm[col], 0.f);
                v.y = fmaxf(v.y + bsm[col + 1], 0.f);
                *(float2*)(Hs + rl * AS_STRIDE + col) = v;
            }
        }
    }
    __syncthreads();
    if (!first) {
        float cs[8], cq[8];
#pragma unroll
        for (int j = 0; j < 8; j++) { cs[j] = 0.f; cq[j] = 0.f; }
#pragma unroll
        for (int i = 0; i < 4; i++) {
            int rl = rg * 4 + i;
            int row = rowbase + rl;
            if (row < N) {
#pragma unroll
                for (int j = 0; j < 4; j++) {
                    float2 v = unpack2(acc[i][j]);
                    int col = cg * 8 + 2 * j;
                    v.x = fmaxf(v.x + rbsm[col], 0.f) + Hs[rl * AS_STRIDE + col];
                    v.y = fmaxf(v.y + rbsm[col + 1], 0.f) + Hs[rl * AS_STRIDE + col + 1];
                    *(float2*)(g_h + (size_t)row * D + col) = v;
                    cs[2 * j]     += v.x;  cq[2 * j]     += v.x * v.x;
                    cs[2 * j + 1] += v.y;  cq[2 * j + 1] += v.y * v.y;
                }
            }
        }
        int rep = (rg & 3) * 128;
#pragma unroll
        for (int j = 0; j < 8; j++) {
            atomicAdd(&scs4[rep + cg * 8 + j], cs[j]);
            atomicAdd(&scq4[rep + cg * 8 + j], cq[j]);
        }
    }
    __syncthreads();
    if (tid < 128) {
        float s = scs4[tid] + scs4[128 + tid] + scs4[256 + tid] + scs4[384 + tid];
        float q = scq4[tid] + scq4[128 + tid] + scq4[256 + tid] + scq4[384 + tid];
        atomicAdd(&g_colsum[tid], s);
        atomicAdd(&g_colsq[tid], q);
    }
}

// ---------------- BN stats finalize ----------------
__global__ void stats_kernel(const float* __restrict__ gamma,
                             const float* __restrict__ beta, int N) {
    int t = threadIdx.x;
    float invN = 1.0f / (float)N;
    float mu = g_colsum[t] * invN;
    float var = g_colsq[t] * invN - mu * mu;
    var = fmaxf(var, 0.f);
    float istd = rsqrtf(var + 1e-5f);
    float sc = gamma[t] * istd;
    g_scale[t] = sc;
    g_shift[t] = beta[t] - mu * sc;
}

// ---------------- final normalize (last layer only) ----------------
__global__ void normalize_kernel(int N, float* __restrict__ out) {
    int total = N * 32;
    for (int idx = blockIdx.x * blockDim.x + threadIdx.x; idx < total;
         idx += gridDim.x * blockDim.x) {
        int c4 = idx & 31;
        float4 v = ((const float4*)g_h)[idx];
        float4 s = ((const float4*)g_scale)[c4];
        float4 sh = ((const float4*)g_shift)[c4];
        float4 r;
        r.x = v.x * s.x + sh.x;
        r.y = v.y * s.y + sh.y;
        r.z = v.z * s.z + sh.z;
        r.w = v.w * s.w + sh.w;
        ((float4*)out)[idx] = r;
    }
}

// ---------------- launch ----------------
extern "C" void kernel_launch(void* const* d_in, const int* in_sizes, int n_in,
                              void* d_out, int out_size) {
    const int*   node_ids = (const int*)d_in[0];
    const int*   src      = (const int*)d_in[1];
    const int*   dst      = (const int*)d_in[2];
    const float* emb      = (const float*)d_in[3];
    const float* Ws       = (const float*)d_in[4];
    const float* bs       = (const float*)d_in[5];
    const float* Rws      = (const float*)d_in[6];
    const float* Rbs      = (const float*)d_in[7];
    const float* gammas   = (const float*)d_in[8];
    const float* betas    = (const float*)d_in[9];

    const int N = in_sizes[0];
    const int E = in_sizes[1];
    const int L = in_sizes[4] / (D * D);
    const int nch = (N + 255) / 256;

    cudaFuncSetAttribute(gemm_kernel,
                         cudaFuncAttributeMaxDynamicSharedMemorySize,
                         SMEM_BYTES);

    // prep: degrees, norms, CSR, embedding gather, identity BN
    prep_kernel<<<(N + 255) / 256, 256>>>(N);
    deg_kernel<<<(E + 255) / 256, 256>>>(src, dst, E);
    scan1_kernel<<<nch, 256>>>(N);
    scan2_kernel<<<1, 256>>>(nch);
    scan3_kernel<<<nch, 256>>>(N, E);
    fill_kernel<<<(E + 255) / 256, 256>>>(src, dst, E);
    gather_kernel<<<(N * 32 + 255) / 256, 256>>>(node_ids, emb, N);

    // layers: gather (BN-folded) -> dual GEMM (+stats) -> stats finalize
    for (int l = 0; l < L; ++l) {
        int use_h = (l > 0) ? 1 : 0;
        gather_agg_kernel<<<(N * 32 + 255) / 256, 256>>>(use_h, N);
        gemm_kernel<<<(N + 63) / 64, 512, SMEM_BYTES>>>(
            Ws + l * D * D, Rws + l * D * D, bs + l * D, Rbs + l * D,
            use_h, N);
        stats_kernel<<<1, 128>>>(gammas + l * D, betas + l * D, N);
    }
    normalize_kernel<<<512, 256>>>(N, (float*)d_out);
}

// round 9
// speedup vs baseline: 1.2564x; 1.2564x over previous
#include <cuda_runtime.h>
#include <cuda_bf16.h>

#define D 128
#define MAXN 50176    // padded N
#define MAXE 524288

// ---------------- scratch (device globals, no allocation) ----------------
__device__ float g_x[MAXN * D];     // embedding (layer-0 input)
__device__ float g_h[MAXN * D];     // pre-BN activations (layer output)
__device__ float g_agg[MAXN * D];
__device__ float g_onorm[MAXN];
__device__ float g_inorm[MAXN];
__device__ float g_colsum[D];
__device__ float g_colsq[D];
__device__ float g_scale[D];        // BN scale of PREVIOUS layer (init 1)
__device__ float g_shift[D];        // BN shift of PREVIOUS layer (init 0)

// CSR structures
__device__ int   g_outdeg[MAXN];
__device__ int   g_indeg[MAXN];
__device__ int   g_rowptr[MAXN + 1];
__device__ int   g_cursor[MAXN];
__device__ int   g_chunksum[256];
__device__ int   g_chunkoff[256];
__device__ int2  g_epack[MAXE];     // (src, onorm-bits)

// ---------------- f32x2 helpers ----------------
__device__ __forceinline__ unsigned long long pack2(float x, float y) {
    unsigned long long r;
    asm("mov.b64 %0, {%1, %2};" : "=l"(r) : "f"(x), "f"(y));
    return r;
}
__device__ __forceinline__ void ffma2(unsigned long long& d,
                                      unsigned long long a,
                                      unsigned long long b) {
    asm("fma.rn.f32x2 %0, %1, %2, %0;" : "+l"(d) : "l"(a), "l"(b));
}
__device__ __forceinline__ float2 unpack2(unsigned long long v) {
    float2 r;
    asm("mov.b64 {%0, %1}, %2;" : "=f"(r.x), "=f"(r.y) : "l"(v));
    return r;
}

// ---------------- prep: zero degrees + identity BN ----------------
__global__ void prep_kernel(int N) {
    int i = blockIdx.x * blockDim.x + threadIdx.x;
    if (i < N) { g_outdeg[i] = 0; g_indeg[i] = 0; }
    if (i < D) { g_scale[i] = 1.0f; g_shift[i] = 0.0f; }
}

__global__ void deg_kernel(const int* __restrict__ src,
                           const int* __restrict__ dst, int E) {
    int e = blockIdx.x * blockDim.x + threadIdx.x;
    if (e < E) {
        atomicAdd(&g_outdeg[src[e]], 1);
        atomicAdd(&g_indeg[dst[e]], 1);
    }
}

// ---------------- scan of indeg -> rowptr; also finalize norms ----------
__global__ void scan1_kernel(int N) {
    __shared__ int sd[256];
    int i = blockIdx.x * 256 + threadIdx.x;
    int dv = (i < N) ? g_indeg[i] : 0;
    sd[threadIdx.x] = dv;
    if (i < N) {
        int a = g_outdeg[i];
        g_onorm[i] = (a > 0) ? rsqrtf((float)a) : 0.f;
        g_inorm[i] = (dv > 0) ? rsqrtf((float)dv) : 0.f;
    }
    __syncthreads();
    for (int s = 128; s > 0; s >>= 1) {
        if (threadIdx.x < s) sd[threadIdx.x] += sd[threadIdx.x + s];
        __syncthreads();
    }
    if (threadIdx.x == 0) g_chunksum[blockIdx.x] = sd[0];
}

__global__ void scan2_kernel(int nch) {
    __shared__ int sd[256];
    int t = threadIdx.x;
    int v = (t < nch) ? g_chunksum[t] : 0;
    sd[t] = v;
    __syncthreads();
    for (int off = 1; off < 256; off <<= 1) {
        int val = (t >= off) ? sd[t - off] : 0;
        __syncthreads();
        sd[t] += val;
        __syncthreads();
    }
    if (t < nch) g_chunkoff[t] = sd[t] - v;  // exclusive
}

__global__ void scan3_kernel(int N, int E) {
    __shared__ int sd[256];
    int t = threadIdx.x;
    int i = blockIdx.x * 256 + t;
    int v = (i < N) ? g_indeg[i] : 0;
    sd[t] = v;
    __syncthreads();
    for (int off = 1; off < 256; off <<= 1) {
        int val = (t >= off) ? sd[t - off] : 0;
        __syncthreads();
        sd[t] += val;
        __syncthreads();
    }
    if (i < N) {
        int rp = g_chunkoff[blockIdx.x] + sd[t] - v;
        g_rowptr[i] = rp;
        g_cursor[i] = rp;
    }
    if (i == 0) g_rowptr[N] = E;
}

__global__ void fill_kernel(const int* __restrict__ src,
                            const int* __restrict__ dst, int E) {
    int e = blockIdx.x * blockDim.x + threadIdx.x;
    if (e < E) {
        int s = src[e];
        int d = dst[e];
        int p = atomicAdd(&g_cursor[d], 1);
        g_epack[p] = make_int2(s, __float_as_int(g_onorm[s]));
    }
}

// ---------------- embedding gather ----------------
__global__ void gather_kernel(const int* __restrict__ node_ids,
                              const float* __restrict__ emb, int N) {
    int gid = blockIdx.x * blockDim.x + threadIdx.x;
    if (gid < N * 32) {
        int i = gid >> 5;
        int c = gid & 31;
        ((float4*)g_x)[gid] = ((const float4*)emb)[node_ids[i] * 32 + c];
    }
}

// ---------------- CSR gather aggregation (BN fold), warp per dst --------
// agg[d] = inorm[d] * ( scale .* sum(w_e*h[s]) + shift * sum(w_e) )
// Also zeroes this layer's BN stat accumulators.
__global__ void gather_agg_kernel(int use_h, int N) {
    int gid = blockIdx.x * blockDim.x + threadIdx.x;
    int w = gid >> 5;
    int lane = gid & 31;
    if (blockIdx.x == 0 && threadIdx.x < 128) {
        g_colsum[threadIdx.x] = 0.f;
        g_colsq[threadIdx.x] = 0.f;
    }
    if (w >= N) return;
    const float* buf = use_h ? g_h : g_x;
    int beg = g_rowptr[w];
    int end = g_rowptr[w + 1];
    float4 acc = make_float4(0.f, 0.f, 0.f, 0.f);
    float sw = 0.f;
#pragma unroll 8
    for (int j = beg; j < end; ++j) {
        int2 e = g_epack[j];
        float wt = __int_as_float(e.y);
        sw += wt;
        float4 v = ((const float4*)buf)[e.x * 32 + lane];
        acc.x += wt * v.x;
        acc.y += wt * v.y;
        acc.z += wt * v.z;
        acc.w += wt * v.w;
    }
    float inn = g_inorm[w];
    float4 sc = ((const float4*)g_scale)[lane];
    float4 sh = ((const float4*)g_shift)[lane];
    float4 o;
    o.x = inn * (sc.x * acc.x + sh.x * sw);
    o.y = inn * (sc.y * acc.y + sh.y * sw);
    o.z = inn * (sc.z * acc.z + sh.z * sw);
    o.w = inn * (sc.w * acc.w + sh.w * sw);
    ((float4*)g_agg)[w * 32 + lane] = o;
}

// ---------------- persistent fused dual GEMM + bias + relu + residual ----
// h = relu(agg @ W + b) + relu(BN(buf) @ Rw + rb);  accumulates column
// sum / sumsq of h into smem, flushed once per block. Weights loaded once,
// block loops over 64-row chunks. R3-proven 256-thread / 8x8-tile mainloop.
#define AS_STRIDE 132
#define SMEM_FLOATS (32768 + 2 * 64 * AS_STRIDE + 256 + 1024)
#define SMEM_BYTES (SMEM_FLOATS * 4)

__global__ __launch_bounds__(256, 1)
void gemm_kernel(const float* __restrict__ W, const float* __restrict__ R,
                 const float* __restrict__ b, const float* __restrict__ rb,
                 int use_h, int N) {
    extern __shared__ float sm[];
    float* Wsm  = sm;                       // 16384
    float* Rsm  = sm + 16384;               // 16384
    float* As   = sm + 32768;               // 8448
    float* Xs   = As + 64 * AS_STRIDE;      // 8448
    float* bsm  = Xs + 64 * AS_STRIDE;      // 128
    float* rbsm = bsm + 128;                // 128
    float* scs4 = rbsm + 128;               // 512 (4 replicas x 128)
    float* scq4 = scs4 + 512;               // 512

    const int tid = threadIdx.x;
    const float* buf = use_h ? g_h : g_x;

    // one-time: weights + biases + zero stat replicas
    for (int idx = tid; idx < 4096; idx += 256) {
        ((float4*)Wsm)[idx] = ((const float4*)W)[idx];
        ((float4*)Rsm)[idx] = ((const float4*)R)[idx];
    }
    if (tid < 128) { bsm[tid] = b[tid]; rbsm[tid] = rb[tid]; }
    for (int idx = tid; idx < 512; idx += 256) {
        scs4[idx] = 0.f;
        scq4[idx] = 0.f;
    }

    const int h = tid & 127;
    const bool first = (tid < 128);
    const float* Mt = first ? As : Xs;
    const float* Wt = first ? Wsm : Rsm;
    const int cg = h & 15;      // cols [cg*8, cg*8+8)
    const int rg = h >> 4;      // rows [rg*8, rg*8+8)
    const float* mrow = Mt + rg * 8 * AS_STRIDE;
    const float* wcol = Wt + cg * 8;
    float* Hs = As;             // reuse As for relu(agg@W + b)

    const int nchunks = (N + 63) / 64;
    for (int chunk = blockIdx.x; chunk < nchunks; chunk += gridDim.x) {
        const int rowbase = chunk * 64;
        __syncthreads();  // previous iteration done with As/Xs/Hs

        // load input tiles: As = agg (pre-folded), Xs = BN(buf)
        for (int idx = tid; idx < 2048; idx += 256) {
            int r = idx >> 5;
            int c4 = idx & 31;
            int row = rowbase + r;
            float4 va = make_float4(0.f, 0.f, 0.f, 0.f);
            float4 vx = va;
            if (row < N) {
                va = ((const float4*)g_agg)[row * 32 + c4];
                float4 v = ((const float4*)buf)[row * 32 + c4];
                float4 sc = ((const float4*)g_scale)[c4];
                float4 sh = ((const float4*)g_shift)[c4];
                vx.x = v.x * sc.x + sh.x;
                vx.y = v.y * sc.y + sh.y;
                vx.z = v.z * sc.z + sh.z;
                vx.w = v.w * sc.w + sh.w;
            }
            *(float4*)(As + r * AS_STRIDE + c4 * 4) = va;
            *(float4*)(Xs + r * AS_STRIDE + c4 * 4) = vx;
        }
        __syncthreads();

        unsigned long long acc[8][4];
#pragma unroll
        for (int i = 0; i < 8; i++)
#pragma unroll
            for (int j = 0; j < 4; j++) acc[i][j] = 0ull;

#pragma unroll 4
        for (int k = 0; k < 128; ++k) {
            ulonglong2 wA = *(const ulonglong2*)(wcol + k * 128);
            ulonglong2 wB = *(const ulonglong2*)(wcol + k * 128 + 4);
#pragma unroll
            for (int i = 0; i < 8; i++) {
                float a = mrow[i * AS_STRIDE + k];
                unsigned long long ad = pack2(a, a);
                ffma2(acc[i][0], ad, wA.x);
                ffma2(acc[i][1], ad, wA.y);
                ffma2(acc[i][2], ad, wB.x);
                ffma2(acc[i][3], ad, wB.y);
            }
        }

        // branch 0 writes relu(agg@W+b) into Hs (=As region; warp-private rows)
        if (first) {
            __syncwarp();
#pragma unroll
            for (int i = 0; i < 8; i++) {
                int rl = rg * 8 + i;
#pragma unroll
                for (int j = 0; j < 4; j++) {
                    float2 v = unpack2(acc[i][j]);
                    int col = cg * 8 + 2 * j;
                    v.x = fmaxf(v.x + bsm[col], 0.f);
                    v.y = fmaxf(v.y + bsm[col + 1], 0.f);
                    *(float2*)(Hs + rl * AS_STRIDE + col) = v;
                }
            }
        }
        __syncthreads();
        // branch 1: add relu(x@Rw+rb), write h, accumulate BN stats
        if (!first) {
            float cs[8], cq[8];
#pragma unroll
            for (int j = 0; j < 8; j++) { cs[j] = 0.f; cq[j] = 0.f; }
#pragma unroll
            for (int i = 0; i < 8; i++) {
                int rl = rg * 8 + i;
                int row = rowbase + rl;
                if (row < N) {
#pragma unroll
                    for (int j = 0; j < 4; j++) {
                        float2 v = unpack2(acc[i][j]);
                        int col = cg * 8 + 2 * j;
                        v.x = fmaxf(v.x + rbsm[col], 0.f) + Hs[rl * AS_STRIDE + col];
                        v.y = fmaxf(v.y + rbsm[col + 1], 0.f) + Hs[rl * AS_STRIDE + col + 1];
                        *(float2*)(g_h + (size_t)row * D + col) = v;
                        cs[2 * j]     += v.x;  cq[2 * j]     += v.x * v.x;
                        cs[2 * j + 1] += v.y;  cq[2 * j + 1] += v.y * v.y;
                    }
                }
            }
            int rep = (rg & 3) * 128;
#pragma unroll
            for (int j = 0; j < 8; j++) {
                atomicAdd(&scs4[rep + cg * 8 + j], cs[j]);
                atomicAdd(&scq4[rep + cg * 8 + j], cq[j]);
            }
        }
    }

    // one-time flush of BN stats
    __syncthreads();
    if (tid < 128) {
        float s = scs4[tid] + scs4[128 + tid] + scs4[256 + tid] + scs4[384 + tid];
        float q = scq4[tid] + scq4[128 + tid] + scq4[256 + tid] + scq4[384 + tid];
        atomicAdd(&g_colsum[tid], s);
        atomicAdd(&g_colsq[tid], q);
    }
}

// ---------------- BN stats finalize ----------------
__global__ void stats_kernel(const float* __restrict__ gamma,
                             const float* __restrict__ beta, int N) {
    int t = threadIdx.x;
    float invN = 1.0f / (float)N;
    float mu = g_colsum[t] * invN;
    float var = g_colsq[t] * invN - mu * mu;
    var = fmaxf(var, 0.f);
    float istd = rsqrtf(var + 1e-5f);
    float sc = gamma[t] * istd;
    g_scale[t] = sc;
    g_shift[t] = beta[t] - mu * sc;
}

// ---------------- final normalize (last layer only) ----------------
__global__ void normalize_kernel(int N, float* __restrict__ out) {
    int total = N * 32;
    for (int idx = blockIdx.x * blockDim.x + threadIdx.x; idx < total;
         idx += gridDim.x * blockDim.x) {
        int c4 = idx & 31;
        float4 v = ((const float4*)g_h)[idx];
        float4 s = ((const float4*)g_scale)[c4];
        float4 sh = ((const float4*)g_shift)[c4];
        float4 r;
        r.x = v.x * s.x + sh.x;
        r.y = v.y * s.y + sh.y;
        r.z = v.z * s.z + sh.z;
        r.w = v.w * s.w + sh.w;
        ((float4*)out)[idx] = r;
    }
}

// ---------------- launch ----------------
extern "C" void kernel_launch(void* const* d_in, const int* in_sizes, int n_in,
                              void* d_out, int out_size) {
    const int*   node_ids = (const int*)d_in[0];
    const int*   src      = (const int*)d_in[1];
    const int*   dst      = (const int*)d_in[2];
    const float* emb      = (const float*)d_in[3];
    const float* Ws       = (const float*)d_in[4];
    const float* bs       = (const float*)d_in[5];
    const float* Rws      = (const float*)d_in[6];
    const float* Rbs      = (const float*)d_in[7];
    const float* gammas   = (const float*)d_in[8];
    const float* betas    = (const float*)d_in[9];

    const int N = in_sizes[0];
    const int E = in_sizes[1];
    const int L = in_sizes[4] / (D * D);
    const int nch = (N + 255) / 256;

    cudaFuncSetAttribute(gemm_kernel,
                         cudaFuncAttributeMaxDynamicSharedMemorySize,
                         SMEM_BYTES);

    // prep: degrees, norms, CSR, embedding gather, identity BN
    prep_kernel<<<(N + 255) / 256, 256>>>(N);
    deg_kernel<<<(E + 255) / 256, 256>>>(src, dst, E);
    scan1_kernel<<<nch, 256>>>(N);
    scan2_kernel<<<1, 256>>>(nch);
    scan3_kernel<<<nch, 256>>>(N, E);
    fill_kernel<<<(E + 255) / 256, 256>>>(src, dst, E);
    gather_kernel<<<(N * 32 + 255) / 256, 256>>>(node_ids, emb, N);

    // layers: gather (BN-folded) -> persistent dual GEMM (+stats) -> stats
    for (int l = 0; l < L; ++l) {
        int use_h = (l > 0) ? 1 : 0;
        gather_agg_kernel<<<(N * 32 + 255) / 256, 256>>>(use_h, N);
        gemm_kernel<<<148, 256, SMEM_BYTES>>>(
            Ws + l * D * D, Rws + l * D * D, bs + l * D, Rbs + l * D,
            use_h, N);
        stats_kernel<<<1, 128>>>(gammas + l * D, betas + l * D, N);
    }
    normalize_kernel<<<512, 256>>>(N, (float*)d_out);
}

// round 10
// speedup vs baseline: 1.9320x; 1.5377x over previous
#include <cuda_runtime.h>
#include <cuda_bf16.h>

#define D 128
#define MAXN 50176    // padded N
#define MAXE 524288
#define LMAX 3

// ---------------- scratch (device globals, no allocation) ----------------
__device__ float g_x[MAXN * D];     // embedding (layer-0 input)
__device__ float g_h[MAXN * D];     // pre-BN activations (layer output)
__device__ float g_agg[MAXN * D];
__device__ float g_onorm[MAXN];
__device__ float g_inorm[MAXN];
__device__ float g_colsum[D];
__device__ float g_colsq[D];
__device__ float g_scale[D];        // BN scale of PREVIOUS layer (init 1)
__device__ float g_shift[D];        // BN shift of PREVIOUS layer (init 0)

// CSR structures
__device__ int   g_outdeg[MAXN];
__device__ int   g_indeg[MAXN];
__device__ int   g_rowptr[MAXN + 1];
__device__ int   g_cursor[MAXN];
__device__ int   g_chunksum[256];
__device__ int   g_chunkoff[256];
__device__ int2  g_epack[MAXE];     // (src, onorm-bits)

// weights pre-split to bf16 hi/lo, pre-permuted into mma B-fragment register
// order: [layer][ {Whi, Wlo, Rhi, Rlo} ][ ((kt*16+nt)*32+lane)*2+reg ][half]
__device__ __align__(16) unsigned short g_bfrag[LMAX][4][16384];

// ---------------- mma / split helpers ----------------
__device__ __forceinline__ void mma16816(float* c, const uint4& a, const uint2& b) {
    asm volatile(
        "mma.sync.aligned.m16n8k16.row.col.f32.bf16.bf16.f32 "
        "{%0,%1,%2,%3}, {%4,%5,%6,%7}, {%8,%9}, {%0,%1,%2,%3};"
        : "+f"(c[0]), "+f"(c[1]), "+f"(c[2]), "+f"(c[3])
        : "r"(a.x), "r"(a.y), "r"(a.z), "r"(a.w), "r"(b.x), "r"(b.y));
}
__device__ __forceinline__ void split2(float x, float y,
                                       unsigned& hi, unsigned& lo) {
    __nv_bfloat162 h2 = __floats2bfloat162_rn(x, y);   // .x = x (low half)
    hi = *(unsigned*)&h2;
    float rx = x - __bfloat162float(h2.x);
    float ry = y - __bfloat162float(h2.y);
    __nv_bfloat162 l2 = __floats2bfloat162_rn(rx, ry);
    lo = *(unsigned*)&l2;
}

// ---------------- prep: zero degrees + identity BN ----------------
__global__ void prep_kernel(int N) {
    int i = blockIdx.x * blockDim.x + threadIdx.x;
    if (i < N) { g_outdeg[i] = 0; g_indeg[i] = 0; }
    if (i < D) { g_scale[i] = 1.0f; g_shift[i] = 0.0f; }
}

// weight split + permute into fragment order (runs once)
__global__ void wprep_kernel(const float* __restrict__ Ws,
                             const float* __restrict__ Rws, int L) {
    int id = blockIdx.x * blockDim.x + threadIdx.x;
    if (id >= L * 32768) return;
    int l = id >> 15;
    int rest = id & 32767;
    int which = rest >> 14;          // 0 = W, 1 = R
    int e = rest & 16383;
    int k = e >> 7, n = e & 127;
    float w = (which ? Rws : Ws)[l * 16384 + k * 128 + n];
    __nv_bfloat16 hb = __float2bfloat16(w);
    __nv_bfloat16 lb = __float2bfloat16(w - __bfloat162float(hb));
    // B fragment (k16 x n8, col): b0 = B[2t][g],B[2t+1][g]; b1 = k+8
    int kt = k >> 4, kk = k & 15, nt = n >> 3, g = n & 7;
    int t = (kk >> 1) & 3, reg = kk >> 3, half = kk & 1;
    int lane = g * 4 + t;
    int slot = ((((kt * 16 + nt) * 32 + lane) * 2 + reg) << 1) + half;
    g_bfrag[l][which * 2 + 0][slot] = *(unsigned short*)&hb;
    g_bfrag[l][which * 2 + 1][slot] = *(unsigned short*)&lb;
}

__global__ void deg_kernel(const int* __restrict__ src,
                           const int* __restrict__ dst, int E) {
    int e = blockIdx.x * blockDim.x + threadIdx.x;
    if (e < E) {
        atomicAdd(&g_outdeg[src[e]], 1);
        atomicAdd(&g_indeg[dst[e]], 1);
    }
}

// ---------------- scan of indeg -> rowptr; also finalize norms ----------
__global__ void scan1_kernel(int N) {
    __shared__ int sd[256];
    int i = blockIdx.x * 256 + threadIdx.x;
    int dv = (i < N) ? g_indeg[i] : 0;
    sd[threadIdx.x] = dv;
    if (i < N) {
        int a = g_outdeg[i];
        g_onorm[i] = (a > 0) ? rsqrtf((float)a) : 0.f;
        g_inorm[i] = (dv > 0) ? rsqrtf((float)dv) : 0.f;
    }
    __syncthreads();
    for (int s = 128; s > 0; s >>= 1) {
        if (threadIdx.x < s) sd[threadIdx.x] += sd[threadIdx.x + s];
        __syncthreads();
    }
    if (threadIdx.x == 0) g_chunksum[blockIdx.x] = sd[0];
}

__global__ void scan2_kernel(int nch) {
    __shared__ int sd[256];
    int t = threadIdx.x;
    int v = (t < nch) ? g_chunksum[t] : 0;
    sd[t] = v;
    __syncthreads();
    for (int off = 1; off < 256; off <<= 1) {
        int val = (t >= off) ? sd[t - off] : 0;
        __syncthreads();
        sd[t] += val;
        __syncthreads();
    }
    if (t < nch) g_chunkoff[t] = sd[t] - v;  // exclusive
}

__global__ void scan3_kernel(int N, int E) {
    __shared__ int sd[256];
    int t = threadIdx.x;
    int i = blockIdx.x * 256 + t;
    int v = (i < N) ? g_indeg[i] : 0;
    sd[t] = v;
    __syncthreads();
    for (int off = 1; off < 256; off <<= 1) {
        int val = (t >= off) ? sd[t - off] : 0;
        __syncthreads();
        sd[t] += val;
        __syncthreads();
    }
    if (i < N) {
        int rp = g_chunkoff[blockIdx.x] + sd[t] - v;
        g_rowptr[i] = rp;
        g_cursor[i] = rp;
    }
    if (i == 0) g_rowptr[N] = E;
}

__global__ void fill_kernel(const int* __restrict__ src,
                            const int* __restrict__ dst, int E) {
    int e = blockIdx.x * blockDim.x + threadIdx.x;
    if (e < E) {
        int s = src[e];
        int d = dst[e];
        int p = atomicAdd(&g_cursor[d], 1);
        g_epack[p] = make_int2(s, __float_as_int(g_onorm[s]));
    }
}

// ---------------- embedding gather ----------------
__global__ void gather_kernel(const int* __restrict__ node_ids,
                              const float* __restrict__ emb, int N) {
    int gid = blockIdx.x * blockDim.x + threadIdx.x;
    if (gid < N * 32) {
        int i = gid >> 5;
        int c = gid & 31;
        ((float4*)g_x)[gid] = ((const float4*)emb)[node_ids[i] * 32 + c];
    }
}

// ---------------- CSR gather aggregation (BN fold), warp per dst --------
__global__ void gather_agg_kernel(int use_h, int N) {
    int gid = blockIdx.x * blockDim.x + threadIdx.x;
    int w = gid >> 5;
    int lane = gid & 31;
    if (blockIdx.x == 0 && threadIdx.x < 128) {
        g_colsum[threadIdx.x] = 0.f;
        g_colsq[threadIdx.x] = 0.f;
    }
    if (w >= N) return;
    const float* buf = use_h ? g_h : g_x;
    int beg = g_rowptr[w];
    int end = g_rowptr[w + 1];
    float4 acc = make_float4(0.f, 0.f, 0.f, 0.f);
    float sw = 0.f;
#pragma unroll 8
    for (int j = beg; j < end; ++j) {
        int2 e = g_epack[j];
        float wt = __int_as_float(e.y);
        sw += wt;
        float4 v = ((const float4*)buf)[e.x * 32 + lane];
        acc.x += wt * v.x;
        acc.y += wt * v.y;
        acc.z += wt * v.z;
        acc.w += wt * v.w;
    }
    float inn = g_inorm[w];
    float4 sc = ((const float4*)g_scale)[lane];
    float4 sh = ((const float4*)g_shift)[lane];
    float4 o;
    o.x = inn * (sc.x * acc.x + sh.x * sw);
    o.y = inn * (sc.y * acc.y + sh.y * sw);
    o.z = inn * (sc.z * acc.z + sh.z * sw);
    o.w = inn * (sc.w * acc.w + sh.w * sw);
    ((float4*)g_agg)[w * 32 + lane] = o;
}

// ---------------- persistent tensor-core dual GEMM (bf16x3) --------------
// h = relu(agg @ W + b) + relu(BN(buf) @ Rw + rb), BN stats in registers.
// 256 threads: warps 0-3 branch W, warps 4-7 branch R; 64 rows/chunk;
// warp tile 32 rows x 64 cols; mma.sync m16n8k16, 3 passes (hi/lo split).
#define SM_BWH  0                      // W hi frags: 32768 B
#define SM_BWL  32768
#define SM_BRH  65536
#define SM_BRL  98304
#define SM_A1H  131072                 // A1 (agg) hi frags: 16384 B
#define SM_A1L  147456
#define SM_A2H  163840
#define SM_A2L  180224
#define SM_BIAS 196608                 // 512 B
#define SM_RB   197120
#define SM_SC   197632
#define SM_SH   198144
#define SM_CS   198656                 // 2048 B (4 replicas x 128)
#define SM_CQ   200704
#define TC_SMEM 202752
// Hs (64x64 float2, xor-swizzled) overlays SM_A1H..SM_A1H+32768

__global__ __launch_bounds__(256, 1)
void gemm_tc_kernel(const float* __restrict__ b, const float* __restrict__ rb,
                    int l, int use_h, int N) {
    extern __shared__ char smc[];
    const int tid = threadIdx.x;
    const int lane = tid & 31;
    const int wid = tid >> 5;
    const bool br1 = (wid >= 4);
    const int wl = wid & 3;
    const int mtbase = (wl & 1) * 2;   // warp's m-tiles: mtbase, mtbase+1
    const int nh = wl >> 1;            // warp's n half (cols nh*64..+63)
    const float* buf = use_h ? g_h : g_x;

    unsigned* A1H = (unsigned*)(smc + SM_A1H);
    unsigned* A1L = (unsigned*)(smc + SM_A1L);
    unsigned* A2H = (unsigned*)(smc + SM_A2H);
    unsigned* A2L = (unsigned*)(smc + SM_A2L);
    float* bsm  = (float*)(smc + SM_BIAS);
    float* rbsm = (float*)(smc + SM_RB);
    float* scsm = (float*)(smc + SM_SC);
    float* shsm = (float*)(smc + SM_SH);
    float* scs4 = (float*)(smc + SM_CS);
    float* scq4 = (float*)(smc + SM_CQ);
    float2* Hp = (float2*)(smc + SM_A1H);

    // one-time: copy pre-permuted weight fragments (128 KB) + vectors
    {
        const uint4* src4 = (const uint4*)g_bfrag[l];
        uint4* dst4 = (uint4*)smc;
        for (int i = tid; i < 8192; i += 256) dst4[i] = src4[i];
        if (tid < 128) {
            bsm[tid] = b[tid];
            rbsm[tid] = rb[tid];
            scsm[tid] = g_scale[tid];
            shsm[tid] = g_shift[tid];
            scs4[tid] = 0.f; scs4[128 + tid] = 0.f;
            scs4[256 + tid] = 0.f; scs4[384 + tid] = 0.f;
            scq4[tid] = 0.f; scq4[128 + tid] = 0.f;
            scq4[256 + tid] = 0.f; scq4[384 + tid] = 0.f;
        }
    }

    const unsigned* Ah = br1 ? A2H : A1H;
    const unsigned* Al = br1 ? A2L : A1L;
    const unsigned* Bh = (const unsigned*)(smc + (br1 ? SM_BRH : SM_BWH));
    const unsigned* Bl = (const unsigned*)(smc + (br1 ? SM_BRL : SM_BWL));

    // BN stats accumulated in registers across all chunks (branch 1 only):
    // column of cs[j*2+h] = nh*64 + j*8 + (lane&3)*2 + h
    float cs[16], cq[16];
#pragma unroll
    for (int i = 0; i < 16; i++) { cs[i] = 0.f; cq[i] = 0.f; }

    const int nchunks = (N + 63) / 64;
    for (int chunk = blockIdx.x; chunk < nchunks; chunk += gridDim.x) {
        const int rowbase = chunk * 64;
        __syncthreads();  // previous chunk fully consumed (Hs/A frags)

        // ---- stage A fragments: A1 = agg, A2 = BN(buf), bf16 hi/lo ----
        for (int idx = tid; idx < 4096; idx += 256) {
            int r = idx >> 6, p = idx & 63;
            int row = rowbase + r;
            float2 va = make_float2(0.f, 0.f);
            float2 vx = va;
            if (row < N) {
                va = ((const float2*)g_agg)[row * 64 + p];
                float2 v = ((const float2*)buf)[row * 64 + p];
                vx.x = v.x * scsm[2 * p] + shsm[2 * p];
                vx.y = v.y * scsm[2 * p + 1] + shsm[2 * p + 1];
            }
            unsigned h1, l1, h2, l2;
            split2(va.x, va.y, h1, l1);
            split2(vx.x, vx.y, h2, l2);
            int mt = r >> 4, rr = r & 15, kt = p >> 3, pp = p & 7;
            int ln = (rr & 7) * 4 + (pp & 3);
            int reg = (rr >> 3) + 2 * (pp >> 2);
            int u = ((mt * 8 + kt) * 32 + ln) * 4 + reg;
            A1H[u] = h1; A1L[u] = l1; A2H[u] = h2; A2L[u] = l2;
        }
        __syncthreads();

        // ---- mma mainloop ----
        float c[2][8][4];
#pragma unroll
        for (int i = 0; i < 2; i++)
#pragma unroll
            for (int j = 0; j < 8; j++)
#pragma unroll
                for (int q = 0; q < 4; q++) c[i][j][q] = 0.f;

#pragma unroll
        for (int kt = 0; kt < 8; ++kt) {
            uint4 ah0 = *(const uint4*)&Ah[(((mtbase + 0) * 8 + kt) * 32 + lane) * 4];
            uint4 ah1 = *(const uint4*)&Ah[(((mtbase + 1) * 8 + kt) * 32 + lane) * 4];
            uint4 al0 = *(const uint4*)&Al[(((mtbase + 0) * 8 + kt) * 32 + lane) * 4];
            uint4 al1 = *(const uint4*)&Al[(((mtbase + 1) * 8 + kt) * 32 + lane) * 4];
#pragma unroll
            for (int j = 0; j < 8; ++j) {
                int nt = nh * 8 + j;
                uint2 bh = *(const uint2*)&Bh[((kt * 16 + nt) * 32 + lane) * 2];
                uint2 bl = *(const uint2*)&Bl[((kt * 16 + nt) * 32 + lane) * 2];
                mma16816(c[0][j], ah0, bh);
                mma16816(c[0][j], ah0, bl);
                mma16816(c[0][j], al0, bh);
                mma16816(c[1][j], ah1, bh);
                mma16816(c[1][j], ah1, bl);
                mma16816(c[1][j], al1, bh);
            }
        }
        __syncthreads();  // all mma done before Hs overlays A1 frags

        // ---- branch 0: Hs = relu(agg@W + b)  (xor-swizzled smem) ----
        if (!br1) {
#pragma unroll
            for (int mt2 = 0; mt2 < 2; ++mt2)
#pragma unroll
                for (int j = 0; j < 8; ++j) {
                    int nt = nh * 8 + j;
                    int r0 = (mtbase + mt2) * 16 + (lane >> 2);
                    int cp = nt * 4 + (lane & 3);
                    float b0v = bsm[cp * 2], b1v = bsm[cp * 2 + 1];
                    float* cc = c[mt2][j];
                    Hp[r0 * 64 + (cp ^ (r0 & 7))] =
                        make_float2(fmaxf(cc[0] + b0v, 0.f),
                                    fmaxf(cc[1] + b1v, 0.f));
                    int r1 = r0 + 8;
                    Hp[r1 * 64 + (cp ^ (r1 & 7))] =
                        make_float2(fmaxf(cc[2] + b0v, 0.f),
                                    fmaxf(cc[3] + b1v, 0.f));
                }
        }
        __syncthreads();

        // ---- branch 1: h = relu(x@Rw + rb) + Hs; write + stats ----
        if (br1) {
#pragma unroll
            for (int mt2 = 0; mt2 < 2; ++mt2)
#pragma unroll
                for (int j = 0; j < 8; ++j) {
                    int nt = nh * 8 + j;
                    int r0 = (mtbase + mt2) * 16 + (lane >> 2);
                    int cp = nt * 4 + (lane & 3);
                    float rb0 = rbsm[cp * 2], rb1 = rbsm[cp * 2 + 1];
                    float* cc = c[mt2][j];
                    int row0 = rowbase + r0;
                    if (row0 < N) {
                        float2 hs = Hp[r0 * 64 + (cp ^ (r0 & 7))];
                        float v0 = fmaxf(cc[0] + rb0, 0.f) + hs.x;
                        float v1 = fmaxf(cc[1] + rb1, 0.f) + hs.y;
                        ((float2*)g_h)[row0 * 64 + cp] = make_float2(v0, v1);
                        cs[j * 2] += v0;     cq[j * 2] += v0 * v0;
                        cs[j * 2 + 1] += v1; cq[j * 2 + 1] += v1 * v1;
                    }
                    int r1 = r0 + 8;
                    int row1 = rowbase + r1;
                    if (row1 < N) {
                        float2 hs = Hp[r1 * 64 + (cp ^ (r1 & 7))];
                        float v0 = fmaxf(cc[2] + rb0, 0.f) + hs.x;
                        float v1 = fmaxf(cc[3] + rb1, 0.f) + hs.y;
                        ((float2*)g_h)[row1 * 64 + cp] = make_float2(v0, v1);
                        cs[j * 2] += v0;     cq[j * 2] += v0 * v0;
                        cs[j * 2 + 1] += v1; cq[j * 2 + 1] += v1 * v1;
                    }
                }
        }
    }

    // ---- flush BN stats: reduce over lane groups, then smem, then global
    __syncthreads();
    if (br1) {
#pragma unroll
        for (int i = 0; i < 16; i++) {
#pragma unroll
            for (int off = 4; off <= 16; off <<= 1) {
                cs[i] += __shfl_xor_sync(0xffffffffu, cs[i], off);
                cq[i] += __shfl_xor_sync(0xffffffffu, cq[i], off);
            }
        }
        if (lane < 4) {
#pragma unroll
            for (int j = 0; j < 8; j++) {
#pragma unroll
                for (int h2 = 0; h2 < 2; h2++) {
                    int col = nh * 64 + j * 8 + lane * 2 + h2;
                    atomicAdd(&scs4[wl * 128 + col], cs[j * 2 + h2]);
                    atomicAdd(&scq4[wl * 128 + col], cq[j * 2 + h2]);
                }
            }
        }
    }
    __syncthreads();
    if (tid < 128) {
        float s = scs4[tid] + scs4[128 + tid] + scs4[256 + tid] + scs4[384 + tid];
        float q = scq4[tid] + scq4[128 + tid] + scq4[256 + tid] + scq4[384 + tid];
        atomicAdd(&g_colsum[tid], s);
        atomicAdd(&g_colsq[tid], q);
    }
}

// ---------------- BN stats finalize ----------------
__global__ void stats_kernel(const float* __restrict__ gamma,
                             const float* __restrict__ beta, int N) {
    int t = threadIdx.x;
    float invN = 1.0f / (float)N;
    float mu = g_colsum[t] * invN;
    float var = g_colsq[t] * invN - mu * mu;
    var = fmaxf(var, 0.f);
    float istd = rsqrtf(var + 1e-5f);
    float sc = gamma[t] * istd;
    g_scale[t] = sc;
    g_shift[t] = beta[t] - mu * sc;
}

// ---------------- final normalize (last layer only) ----------------
__global__ void normalize_kernel(int N, float* __restrict__ out) {
    int total = N * 32;
    for (int idx = blockIdx.x * blockDim.x + threadIdx.x; idx < total;
         idx += gridDim.x * blockDim.x) {
        int c4 = idx & 31;
        float4 v = ((const float4*)g_h)[idx];
        float4 s = ((const float4*)g_scale)[c4];
        float4 sh = ((const float4*)g_shift)[c4];
        float4 r;
        r.x = v.x * s.x + sh.x;
        r.y = v.y * s.y + sh.y;
        r.z = v.z * s.z + sh.z;
        r.w = v.w * s.w + sh.w;
        ((float4*)out)[idx] = r;
    }
}

// ---------------- launch ----------------
extern "C" void kernel_launch(void* const* d_in, const int* in_sizes, int n_in,
                              void* d_out, int out_size) {
    const int*   node_ids = (const int*)d_in[0];
    const int*   src      = (const int*)d_in[1];
    const int*   dst      = (const int*)d_in[2];
    const float* emb      = (const float*)d_in[3];
    const float* Ws       = (const float*)d_in[4];
    const float* bs       = (const float*)d_in[5];
    const float* Rws      = (const float*)d_in[6];
    const float* Rbs      = (const float*)d_in[7];
    const float* gammas   = (const float*)d_in[8];
    const float* betas    = (const float*)d_in[9];

    const int N = in_sizes[0];
    const int E = in_sizes[1];
    const int L = in_sizes[4] / (D * D);
    const int nch = (N + 255) / 256;

    cudaFuncSetAttribute(gemm_tc_kernel,
                         cudaFuncAttributeMaxDynamicSharedMemorySize, TC_SMEM);

    // prep: degrees, norms, CSR, weights->fragments, embedding gather
    prep_kernel<<<(N + 255) / 256, 256>>>(N);
    wprep_kernel<<<(L * 32768 + 255) / 256, 256>>>(Ws, Rws, L);
    deg_kernel<<<(E + 255) / 256, 256>>>(src, dst, E);
    scan1_kernel<<<nch, 256>>>(N);
    scan2_kernel<<<1, 256>>>(nch);
    scan3_kernel<<<nch, 256>>>(N, E);
    fill_kernel<<<(E + 255) / 256, 256>>>(src, dst, E);
    gather_kernel<<<(N * 32 + 255) / 256, 256>>>(node_ids, emb, N);

    // layers: gather (BN-folded) -> persistent tc GEMM (+stats) -> stats
    for (int l = 0; l < L; ++l) {
        int use_h = (l > 0) ? 1 : 0;
        gather_agg_kernel<<<(N * 32 + 255) / 256, 256>>>(use_h, N);
        gemm_tc_kernel<<<148, 256, TC_SMEM>>>(
            bs + l * D, Rbs + l * D, l, use_h, N);
        stats_kernel<<<1, 128>>>(gammas + l * D, betas + l * D, N);
    }
    normalize_kernel<<<512, 256>>>(N, (float*)d_out);
}

// round 12
// speedup vs baseline: 2.0679x; 1.0704x over previous
#include <cuda_runtime.h>
#include <cuda_bf16.h>

#define D 128
#define MAXN 50176    // padded N
#define MAXE 524288
#define LMAX 3

// ---------------- scratch (device globals, no allocation) ----------------
__device__ float g_x[MAXN * D];     // embedding (layer-0 input)
__device__ float g_h[MAXN * D];     // pre-BN activations (layer output)
__device__ float g_agg[MAXN * D];
__device__ float g_inorm[MAXN];
__device__ float g_colsum[D];
__device__ float g_colsq[D];
__device__ float g_scale[D];        // BN scale of PREVIOUS layer (init 1)
__device__ float g_shift[D];        // BN shift of PREVIOUS layer (init 0)

// CSR structures
__device__ int   g_outdeg[MAXN];
__device__ int   g_indeg[MAXN];
__device__ int   g_rowptr[MAXN + 1];
__device__ int   g_cursor[MAXN];
__device__ int   g_chunksum[256];
__device__ int   g_chunkoff[256];
__device__ int2  g_epack[MAXE];     // (src, onorm-bits)

// weights pre-split to bf16 hi/lo, pre-permuted into mma B-fragment order
__device__ __align__(16) unsigned short g_bfrag[LMAX][4][16384];

// ---------------- mma / split helpers ----------------
__device__ __forceinline__ void mma16816(float* c, const uint4& a, const uint2& b) {
    asm volatile(
        "mma.sync.aligned.m16n8k16.row.col.f32.bf16.bf16.f32 "
        "{%0,%1,%2,%3}, {%4,%5,%6,%7}, {%8,%9}, {%0,%1,%2,%3};"
        : "+f"(c[0]), "+f"(c[1]), "+f"(c[2]), "+f"(c[3])
        : "r"(a.x), "r"(a.y), "r"(a.z), "r"(a.w), "r"(b.x), "r"(b.y));
}
__device__ __forceinline__ void split2(float x, float y,
                                       unsigned& hi, unsigned& lo) {
    __nv_bfloat162 h2 = __floats2bfloat162_rn(x, y);
    hi = *(unsigned*)&h2;
    float rx = x - __bfloat162float(h2.x);
    float ry = y - __bfloat162float(h2.y);
    __nv_bfloat162 l2 = __floats2bfloat162_rn(rx, ry);
    lo = *(unsigned*)&l2;
}

// ---------------- init: zero degrees, identity BN, weight fragments ------
__global__ void init_kernel(const float* __restrict__ Ws,
                            const float* __restrict__ Rws, int L, int N) {
    int id = blockIdx.x * blockDim.x + threadIdx.x;
    if (id < N) { g_outdeg[id] = 0; g_indeg[id] = 0; }
    if (id < D) {
        g_scale[id] = 1.0f; g_shift[id] = 0.0f;
        g_colsum[id] = 0.0f; g_colsq[id] = 0.0f;
    }
    if (id >= L * 32768) return;
    int l = id >> 15;
    int rest = id & 32767;
    int which = rest >> 14;          // 0 = W, 1 = R
    int e = rest & 16383;
    int k = e >> 7, n = e & 127;
    float w = (which ? Rws : Ws)[l * 16384 + k * 128 + n];
    __nv_bfloat16 hb = __float2bfloat16(w);
    __nv_bfloat16 lb = __float2bfloat16(w - __bfloat162float(hb));
    int kt = k >> 4, kk = k & 15, nt = n >> 3, g = n & 7;
    int t = (kk >> 1) & 3, reg = kk >> 3, half = kk & 1;
    int lane = g * 4 + t;
    int slot = ((((kt * 16 + nt) * 32 + lane) * 2 + reg) << 1) + half;
    g_bfrag[l][which * 2 + 0][slot] = *(unsigned short*)&hb;
    g_bfrag[l][which * 2 + 1][slot] = *(unsigned short*)&lb;
}

__global__ void deg_kernel(const int* __restrict__ src,
                           const int* __restrict__ dst, int E) {
    int e = blockIdx.x * blockDim.x + threadIdx.x;
    if (e < E) {
        atomicAdd(&g_outdeg[src[e]], 1);
        atomicAdd(&g_indeg[dst[e]], 1);
    }
}

// ---------------- scan of indeg -> rowptr; inorm finalize in scan1 -------
__global__ void scan1_kernel(int N) {
    __shared__ int sd[256];
    int i = blockIdx.x * 256 + threadIdx.x;
    int dv = (i < N) ? g_indeg[i] : 0;
    sd[threadIdx.x] = dv;
    if (i < N) g_inorm[i] = (dv > 0) ? rsqrtf((float)dv) : 0.f;
    __syncthreads();
    for (int s = 128; s > 0; s >>= 1) {
        if (threadIdx.x < s) sd[threadIdx.x] += sd[threadIdx.x + s];
        __syncthreads();
    }
    if (threadIdx.x == 0) g_chunksum[blockIdx.x] = sd[0];
}

__global__ void scan2_kernel(int nch) {
    __shared__ int sd[256];
    int t = threadIdx.x;
    int v = (t < nch) ? g_chunksum[t] : 0;
    sd[t] = v;
    __syncthreads();
    for (int off = 1; off < 256; off <<= 1) {
        int val = (t >= off) ? sd[t - off] : 0;
        __syncthreads();
        sd[t] += val;
        __syncthreads();
    }
    if (t < nch) g_chunkoff[t] = sd[t] - v;  // exclusive
}

__global__ void scan3_kernel(int N, int E) {
    __shared__ int sd[256];
    int t = threadIdx.x;
    int i = blockIdx.x * 256 + t;
    int v = (i < N) ? g_indeg[i] : 0;
    sd[t] = v;
    __syncthreads();
    for (int off = 1; off < 256; off <<= 1) {
        int val = (t >= off) ? sd[t - off] : 0;
        __syncthreads();
        sd[t] += val;
        __syncthreads();
    }
    if (i < N) {
        int rp = g_chunkoff[blockIdx.x] + sd[t] - v;
        g_rowptr[i] = rp;
        g_cursor[i] = rp;
    }
    if (i == 0) g_rowptr[N] = E;
}

// fill: onorm computed inline (src always has outdeg >= 1)
__global__ void fill_kernel(const int* __restrict__ src,
                            const int* __restrict__ dst, int E) {
    int e = blockIdx.x * blockDim.x + threadIdx.x;
    if (e < E) {
        int s = src[e];
        int d = dst[e];
        float wt = rsqrtf((float)g_outdeg[s]);
        int p = atomicAdd(&g_cursor[d], 1);
        g_epack[p] = make_int2(s, __float_as_int(wt));
    }
}

// ---------------- embedding gather ----------------
__global__ void gather_kernel(const int* __restrict__ node_ids,
                              const float* __restrict__ emb, int N) {
    int gid = blockIdx.x * blockDim.x + threadIdx.x;
    if (gid < N * 32) {
        int i = gid >> 5;
        int c = gid & 31;
        ((float4*)g_x)[gid] = ((const float4*)emb)[node_ids[i] * 32 + c];
    }
}

// ---------------- CSR gather aggregation (BN fold), warp per dst --------
__global__ void gather_agg_kernel(int use_h, int N) {
    int gid = blockIdx.x * blockDim.x + threadIdx.x;
    int w = gid >> 5;
    int lane = gid & 31;
    if (w >= N) return;
    const float* buf = use_h ? g_h : g_x;
    int beg = g_rowptr[w];
    int end = g_rowptr[w + 1];
    float4 acc = make_float4(0.f, 0.f, 0.f, 0.f);
    float sw = 0.f;
#pragma unroll 8
    for (int j = beg; j < end; ++j) {
        int2 e = g_epack[j];
        float wt = __int_as_float(e.y);
        sw += wt;
        float4 v = ((const float4*)buf)[e.x * 32 + lane];
        acc.x += wt * v.x;
        acc.y += wt * v.y;
        acc.z += wt * v.z;
        acc.w += wt * v.w;
    }
    float inn = g_inorm[w];
    float4 sc = ((const float4*)g_scale)[lane];
    float4 sh = ((const float4*)g_shift)[lane];
    float4 o;
    o.x = inn * (sc.x * acc.x + sh.x * sw);
    o.y = inn * (sc.y * acc.y + sh.y * sw);
    o.z = inn * (sc.z * acc.z + sh.z * sw);
    o.w = inn * (sc.w * acc.w + sh.w * sw);
    ((float4*)g_agg)[w * 32 + lane] = o;
}

// ---------------- persistent tensor-core dual GEMM (bf16x3) --------------
// h = relu(agg @ W + b) + relu(BN(buf) @ Rw + rb); BN stats in registers.
// Register-prefetched staging: next chunk's rows load during current mma.
#define SM_BWH  0
#define SM_BWL  32768
#define SM_BRH  65536
#define SM_BRL  98304
#define SM_A1H  131072
#define SM_A1L  147456
#define SM_A2H  163840
#define SM_A2L  180224
#define SM_BIAS 196608
#define SM_RB   197120
#define SM_SC   197632
#define SM_SH   198144
#define SM_CS   198656
#define SM_CQ   200704
#define TC_SMEM 202752
// Hs (64x64 float2, xor-swizzled) overlays SM_A1H..SM_A1H+32768

__global__ __launch_bounds__(256, 1)
void gemm_tc_kernel(const float* __restrict__ b, const float* __restrict__ rb,
                    int l, int use_h, int N) {
    extern __shared__ char smc[];
    const int tid = threadIdx.x;
    const int lane = tid & 31;
    const int wid = tid >> 5;
    const bool br1 = (wid >= 4);
    const int wl = wid & 3;
    const int mtbase = (wl & 1) * 2;
    const int nh = wl >> 1;
    const float* buf = use_h ? g_h : g_x;

    unsigned* A1H = (unsigned*)(smc + SM_A1H);
    unsigned* A1L = (unsigned*)(smc + SM_A1L);
    unsigned* A2H = (unsigned*)(smc + SM_A2H);
    unsigned* A2L = (unsigned*)(smc + SM_A2L);
    float* bsm  = (float*)(smc + SM_BIAS);
    float* rbsm = (float*)(smc + SM_RB);
    float* scsm = (float*)(smc + SM_SC);
    float* shsm = (float*)(smc + SM_SH);
    float* scs4 = (float*)(smc + SM_CS);
    float* scq4 = (float*)(smc + SM_CQ);
    float2* Hp = (float2*)(smc + SM_A1H);

    // one-time: copy pre-permuted weight fragments (128 KB) + vectors
    {
        const uint4* src4 = (const uint4*)g_bfrag[l];
        uint4* dst4 = (uint4*)smc;
        for (int i = tid; i < 8192; i += 256) dst4[i] = src4[i];
        if (tid < 128) {
            bsm[tid] = b[tid];
            rbsm[tid] = rb[tid];
            scsm[tid] = g_scale[tid];
            shsm[tid] = g_shift[tid];
            scs4[tid] = 0.f; scs4[128 + tid] = 0.f;
            scs4[256 + tid] = 0.f; scs4[384 + tid] = 0.f;
            scq4[tid] = 0.f; scq4[128 + tid] = 0.f;
            scq4[256 + tid] = 0.f; scq4[384 + tid] = 0.f;
        }
    }

    const unsigned* Ah = br1 ? A2H : A1H;
    const unsigned* Al = br1 ? A2L : A1L;
    const unsigned* Bh = (const unsigned*)(smc + (br1 ? SM_BRH : SM_BWH));
    const unsigned* Bl = (const unsigned*)(smc + (br1 ? SM_BRL : SM_BWL));

    float cs[16], cq[16];
#pragma unroll
    for (int i = 0; i < 16; i++) { cs[i] = 0.f; cq[i] = 0.f; }

    const int nchunks = (N + 63) / 64;
    // per-thread staging coordinates: 8 float4-groups (idx = tid + it*256)
    // r = idx>>5 (row 0..63), q = idx&31 (float4 group = cols 4q..4q+3)
    float4 pa[8], px[8];
    {   // prefetch first chunk
        int rb0 = blockIdx.x * 64;
#pragma unroll
        for (int it = 0; it < 8; ++it) {
            int idx = tid + it * 256;
            int row = rb0 + (idx >> 5);
            int q = idx & 31;
            float4 z = make_float4(0.f, 0.f, 0.f, 0.f);
            pa[it] = z; px[it] = z;
            if (row < N) {
                pa[it] = ((const float4*)g_agg)[row * 32 + q];
                px[it] = ((const float4*)buf)[row * 32 + q];
            }
        }
    }

    for (int chunk = blockIdx.x; chunk < nchunks; chunk += gridDim.x) {
        const int rowbase = chunk * 64;
        __syncthreads();  // previous chunk fully consumed (Hs/A frags)

        // ---- stage prefetched rows into fragments (A1=agg, A2=BN(buf)) --
#pragma unroll
        for (int it = 0; it < 8; ++it) {
            int idx = tid + it * 256;
            int r = idx >> 5, q = idx & 31;
            float4 va = pa[it];
            float4 vb = px[it];
            float4 sc = ((const float4*)scsm)[q];
            float4 sh = ((const float4*)shsm)[q];
            float4 vx;
            vx.x = vb.x * sc.x + sh.x;
            vx.y = vb.y * sc.y + sh.y;
            vx.z = vb.z * sc.z + sh.z;
            vx.w = vb.w * sc.w + sh.w;
            unsigned h1a, l1a, h1b, l1b, h2a, l2a, h2b, l2b;
            split2(va.x, va.y, h1a, l1a);
            split2(va.z, va.w, h1b, l1b);
            split2(vx.x, vx.y, h2a, l2a);
            split2(vx.z, vx.w, h2b, l2b);
            int p0 = 2 * q, p1 = 2 * q + 1;
            int mt = r >> 4, rr = r & 15;
            int kt = p0 >> 3;
            int pp0 = p0 & 7, pp1 = p1 & 7;
            int ln0 = (rr & 7) * 4 + (pp0 & 3);
            int ln1 = (rr & 7) * 4 + (pp1 & 3);
            int rg0 = (rr >> 3) + 2 * (pp0 >> 2);
            int rg1 = (rr >> 3) + 2 * (pp1 >> 2);
            int u0 = ((mt * 8 + kt) * 32 + ln0) * 4 + rg0;
            int u1 = ((mt * 8 + kt) * 32 + ln1) * 4 + rg1;
            A1H[u0] = h1a; A1L[u0] = l1a;
            A1H[u1] = h1b; A1L[u1] = l1b;
            A2H[u0] = h2a; A2L[u0] = l2a;
            A2H[u1] = h2b; A2L[u1] = l2b;
        }
        __syncthreads();

        // ---- issue prefetch for next chunk (hides L2 under mma) ----
        int nextbase = rowbase + gridDim.x * 64;
        if (nextbase < N) {
#pragma unroll
            for (int it = 0; it < 8; ++it) {
                int idx = tid + it * 256;
                int row = nextbase + (idx >> 5);
                int q = idx & 31;
                float4 z = make_float4(0.f, 0.f, 0.f, 0.f);
                pa[it] = z; px[it] = z;
                if (row < N) {
                    pa[it] = ((const float4*)g_agg)[row * 32 + q];
                    px[it] = ((const float4*)buf)[row * 32 + q];
                }
            }
        }

        // ---- mma mainloop ----
        float c[2][8][4];
#pragma unroll
        for (int i = 0; i < 2; i++)
#pragma unroll
            for (int j = 0; j < 8; j++)
#pragma unroll
                for (int q = 0; q < 4; q++) c[i][j][q] = 0.f;

#pragma unroll
        for (int kt = 0; kt < 8; ++kt) {
            uint4 ah0 = *(const uint4*)&Ah[(((mtbase + 0) * 8 + kt) * 32 + lane) * 4];
            uint4 ah1 = *(const uint4*)&Ah[(((mtbase + 1) * 8 + kt) * 32 + lane) * 4];
            uint4 al0 = *(const uint4*)&Al[(((mtbase + 0) * 8 + kt) * 32 + lane) * 4];
            uint4 al1 = *(const uint4*)&Al[(((mtbase + 1) * 8 + kt) * 32 + lane) * 4];
#pragma unroll
            for (int j = 0; j < 8; ++j) {
                int nt = nh * 8 + j;
                uint2 bh = *(const uint2*)&Bh[((kt * 16 + nt) * 32 + lane) * 2];
                uint2 bl = *(const uint2*)&Bl[((kt * 16 + nt) * 32 + lane) * 2];
                mma16816(c[0][j], ah0, bh);
                mma16816(c[0][j], ah0, bl);
                mma16816(c[0][j], al0, bh);
                mma16816(c[1][j], ah1, bh);
                mma16816(c[1][j], ah1, bl);
                mma16816(c[1][j], al1, bh);
            }
        }
        __syncthreads();  // all mma done before Hs overlays A1 frags

        // ---- branch 0: Hs = relu(agg@W + b)  (xor-swizzled smem) ----
        if (!br1) {
#pragma unroll
            for (int mt2 = 0; mt2 < 2; ++mt2)
#pragma unroll
                for (int j = 0; j < 8; ++j) {
                    int nt = nh * 8 + j;
                    int r0 = (mtbase + mt2) * 16 + (lane >> 2);
                    int cp = nt * 4 + (lane & 3);
                    float b0v = bsm[cp * 2], b1v = bsm[cp * 2 + 1];
                    float* cc = c[mt2][j];
                    Hp[r0 * 64 + (cp ^ (r0 & 7))] =
                        make_float2(fmaxf(cc[0] + b0v, 0.f),
                                    fmaxf(cc[1] + b1v, 0.f));
                    int r1 = r0 + 8;
                    Hp[r1 * 64 + (cp ^ (r1 & 7))] =
                        make_float2(fmaxf(cc[2] + b0v, 0.f),
                                    fmaxf(cc[3] + b1v, 0.f));
                }
        }
        __syncthreads();

        // ---- branch 1: h = relu(x@Rw + rb) + Hs; write + stats ----
        if (br1) {
#pragma unroll
            for (int mt2 = 0; mt2 < 2; ++mt2)
#pragma unroll
                for (int j = 0; j < 8; ++j) {
                    int nt = nh * 8 + j;
                    int r0 = (mtbase + mt2) * 16 + (lane >> 2);
                    int cp = nt * 4 + (lane & 3);
                    float rb0 = rbsm[cp * 2], rb1 = rbsm[cp * 2 + 1];
                    float* cc = c[mt2][j];
                    int row0 = rowbase + r0;
                    if (row0 < N) {
                        float2 hs = Hp[r0 * 64 + (cp ^ (r0 & 7))];
                        float v0 = fmaxf(cc[0] + rb0, 0.f) + hs.x;
                        float v1 = fmaxf(cc[1] + rb1, 0.f) + hs.y;
                        ((float2*)g_h)[row0 * 64 + cp] = make_float2(v0, v1);
                        cs[j * 2] += v0;     cq[j * 2] += v0 * v0;
                        cs[j * 2 + 1] += v1; cq[j * 2 + 1] += v1 * v1;
                    }
                    int r1 = r0 + 8;
                    int row1 = rowbase + r1;
                    if (row1 < N) {
                        float2 hs = Hp[r1 * 64 + (cp ^ (r1 & 7))];
                        float v0 = fmaxf(cc[2] + rb0, 0.f) + hs.x;
                        float v1 = fmaxf(cc[3] + rb1, 0.f) + hs.y;
                        ((float2*)g_h)[row1 * 64 + cp] = make_float2(v0, v1);
                        cs[j * 2] += v0;     cq[j * 2] += v0 * v0;
                        cs[j * 2 + 1] += v1; cq[j * 2 + 1] += v1 * v1;
                    }
                }
        }
    }

    // ---- flush BN stats ----
    __syncthreads();
    if (br1) {
#pragma unroll
        for (int i = 0; i < 16; i++) {
#pragma unroll
            for (int off = 4; off <= 16; off <<= 1) {
                cs[i] += __shfl_xor_sync(0xffffffffu, cs[i], off);
                cq[i] += __shfl_xor_sync(0xffffffffu, cq[i], off);
            }
        }
        if (lane < 4) {
#pragma unroll
            for (int j = 0; j < 8; j++) {
#pragma unroll
                for (int h2 = 0; h2 < 2; h2++) {
                    int col = nh * 64 + j * 8 + lane * 2 + h2;
                    atomicAdd(&scs4[wl * 128 + col], cs[j * 2 + h2]);
                    atomicAdd(&scq4[wl * 128 + col], cq[j * 2 + h2]);
                }
            }
        }
    }
    __syncthreads();
    if (tid < 128) {
        float s = scs4[tid] + scs4[128 + tid] + scs4[256 + tid] + scs4[384 + tid];
        float q = scq4[tid] + scq4[128 + tid] + scq4[256 + tid] + scq4[384 + tid];
        atomicAdd(&g_colsum[tid], s);
        atomicAdd(&g_colsq[tid], q);
    }
}

// ---------------- BN stats finalize (zeroes accumulators after read) -----
__global__ void stats_kernel(const float* __restrict__ gamma,
                             const float* __restrict__ beta, int N) {
    int t = threadIdx.x;
    float invN = 1.0f / (float)N;
    float mu = g_colsum[t] * invN;
    float var = g_colsq[t] * invN - mu * mu;
    var = fmaxf(var, 0.f);
    float istd = rsqrtf(var + 1e-5f);
    float sc = gamma[t] * istd;
    g_scale[t] = sc;
    g_shift[t] = beta[t] - mu * sc;
    g_colsum[t] = 0.f;
    g_colsq[t] = 0.f;
}

// ---------------- final normalize (last layer only) ----------------
__global__ void normalize_kernel(int N, float* __restrict__ out) {
    int total = N * 32;
    for (int idx = blockIdx.x * blockDim.x + threadIdx.x; idx < total;
         idx += gridDim.x * blockDim.x) {
        int c4 = idx & 31;
        float4 v = ((const float4*)g_h)[idx];
        float4 s = ((const float4*)g_scale)[c4];
        float4 sh = ((const float4*)g_shift)[c4];
        float4 r;
        r.x = v.x * s.x + sh.x;
        r.y = v.y * s.y + sh.y;
        r.z = v.z * s.z + sh.z;
        r.w = v.w * s.w + sh.w;
        ((float4*)out)[idx] = r;
    }
}

// ---------------- launch ----------------
extern "C" void kernel_launch(void* const* d_in, const int* in_sizes, int n_in,
                              void* d_out, int out_size) {
    const int*   node_ids = (const int*)d_in[0];
    const int*   src      = (const int*)d_in[1];
    const int*   dst      = (const int*)d_in[2];
    const float* emb      = (const float*)d_in[3];
    const float* Ws       = (const float*)d_in[4];
    const float* bs       = (const float*)d_in[5];
    const float* Rws      = (const float*)d_in[6];
    const float* Rbs      = (const float*)d_in[7];
    const float* gammas   = (const float*)d_in[8];
    const float* betas    = (const float*)d_in[9];

    const int N = in_sizes[0];
    const int E = in_sizes[1];
    const int L = in_sizes[4] / (D * D);
    const int nch = (N + 255) / 256;

    cudaFuncSetAttribute(gemm_tc_kernel,
                         cudaFuncAttributeMaxDynamicSharedMemorySize, TC_SMEM);

    // prep: init (zero deg + identity BN + weight frags), degrees, scans,
    // fill (inline onorm), embedding gather
    int ithreads = L * 32768 > N ? L * 32768 : N;
    init_kernel<<<(ithreads + 255) / 256, 256>>>(Ws, Rws, L, N);
    deg_kernel<<<(E + 255) / 256, 256>>>(src, dst, E);
    scan1_kernel<<<nch, 256>>>(N);
    scan2_kernel<<<1, 256>>>(nch);
    scan3_kernel<<<nch, 256>>>(N, E);
    fill_kernel<<<(E + 255) / 256, 256>>>(src, dst, E);
    gather_kernel<<<(N * 32 + 255) / 256, 256>>>(node_ids, emb, N);

    // layers: gather (BN-folded) -> persistent tc GEMM (+stats) -> stats
    for (int l = 0; l < L; ++l) {
        int use_h = (l > 0) ? 1 : 0;
        gather_agg_kernel<<<(N * 32 + 255) / 256, 256>>>(use_h, N);
        gemm_tc_kernel<<<148, 256, TC_SMEM>>>(
            bs + l * D, Rbs + l * D, l, use_h, N);
        stats_kernel<<<1, 128>>>(gammas + l * D, betas + l * D, N);
    }
    normalize_kernel<<<512, 256>>>(N, (float*)d_out);
}

// round 13
// speedup vs baseline: 2.0997x; 1.0154x over previous
#include <cuda_runtime.h>
#include <cuda_bf16.h>

#define D 128
#define MAXN 50176    // padded N
#define MAXE 524288
#define LMAX 3

// ---------------- scratch (device globals, no allocation) ----------------
__device__ float g_x[MAXN * D];     // embedding (layer-0 input)
__device__ float g_h[MAXN * D];     // pre-BN activations (layer output)
__device__ float g_agg[MAXN * D];
__device__ float g_inorm[MAXN];
__device__ float g_colsum[D];
__device__ float g_colsq[D];
__device__ float g_scale[D];        // BN scale of PREVIOUS layer (init 1)
__device__ float g_shift[D];        // BN shift of PREVIOUS layer (init 0)
__device__ unsigned g_blkdone;      // last-block counter for fused stats

// CSR structures
__device__ int   g_outdeg[MAXN];
__device__ int   g_indeg[MAXN];
__device__ int   g_rowptr[MAXN + 1];
__device__ int   g_cursor[MAXN];
__device__ int   g_chunksum[256];
__device__ int   g_chunkoff[256];
__device__ int2  g_epack[MAXE];     // (src, onorm-bits)
__device__ int2  g_epack0[MAXE];    // (node_id[src], onorm-bits) for layer 0

// weights pre-split to bf16 hi/lo, pre-permuted into mma B-fragment order
__device__ __align__(16) unsigned short g_bfrag[LMAX][4][16384];

// ---------------- mma / split helpers ----------------
__device__ __forceinline__ void mma16816(float* c, const uint4& a, const uint2& b) {
    asm volatile(
        "mma.sync.aligned.m16n8k16.row.col.f32.bf16.bf16.f32 "
        "{%0,%1,%2,%3}, {%4,%5,%6,%7}, {%8,%9}, {%0,%1,%2,%3};"
        : "+f"(c[0]), "+f"(c[1]), "+f"(c[2]), "+f"(c[3])
        : "r"(a.x), "r"(a.y), "r"(a.z), "r"(a.w), "r"(b.x), "r"(b.y));
}
__device__ __forceinline__ void split2(float x, float y,
                                       unsigned& hi, unsigned& lo) {
    __nv_bfloat162 h2 = __floats2bfloat162_rn(x, y);
    hi = *(unsigned*)&h2;
    float rx = x - __bfloat162float(h2.x);
    float ry = y - __bfloat162float(h2.y);
    __nv_bfloat162 l2 = __floats2bfloat162_rn(rx, ry);
    lo = *(unsigned*)&l2;
}

// ---------------- init: zero deg, identity BN, weight frags, emb gather --
__global__ void init_kernel(const int* __restrict__ node_ids,
                            const float* __restrict__ emb,
                            const float* __restrict__ Ws,
                            const float* __restrict__ Rws, int L, int N) {
    int id = blockIdx.x * blockDim.x + threadIdx.x;
    if (id == 0) g_blkdone = 0u;
    if (id < N) { g_outdeg[id] = 0; g_indeg[id] = 0; }
    if (id < D) {
        g_scale[id] = 1.0f; g_shift[id] = 0.0f;
        g_colsum[id] = 0.0f; g_colsq[id] = 0.0f;
    }
    if (id < N * 32) {
        int i = id >> 5;
        int c = id & 31;
        ((float4*)g_x)[id] = ((const float4*)emb)[node_ids[i] * 32 + c];
    }
    if (id < L * 32768) {
        int l = id >> 15;
        int rest = id & 32767;
        int which = rest >> 14;          // 0 = W, 1 = R
        int e = rest & 16383;
        int k = e >> 7, n = e & 127;
        float w = (which ? Rws : Ws)[l * 16384 + k * 128 + n];
        __nv_bfloat16 hb = __float2bfloat16(w);
        __nv_bfloat16 lb = __float2bfloat16(w - __bfloat162float(hb));
        int kt = k >> 4, kk = k & 15, nt = n >> 3, g = n & 7;
        int t = (kk >> 1) & 3, reg = kk >> 3, half = kk & 1;
        int lane = g * 4 + t;
        int slot = ((((kt * 16 + nt) * 32 + lane) * 2 + reg) << 1) + half;
        g_bfrag[l][which * 2 + 0][slot] = *(unsigned short*)&hb;
        g_bfrag[l][which * 2 + 1][slot] = *(unsigned short*)&lb;
    }
}

__global__ void deg_kernel(const int* __restrict__ src,
                           const int* __restrict__ dst, int E) {
    int e = blockIdx.x * blockDim.x + threadIdx.x;
    if (e < E) {
        atomicAdd(&g_outdeg[src[e]], 1);
        atomicAdd(&g_indeg[dst[e]], 1);
    }
}

// ---------------- scan of indeg -> rowptr; inorm finalize in scan1 -------
__global__ void scan1_kernel(int N) {
    __shared__ int sd[256];
    int i = blockIdx.x * 256 + threadIdx.x;
    int dv = (i < N) ? g_indeg[i] : 0;
    sd[threadIdx.x] = dv;
    if (i < N) g_inorm[i] = (dv > 0) ? rsqrtf((float)dv) : 0.f;
    __syncthreads();
    for (int s = 128; s > 0; s >>= 1) {
        if (threadIdx.x < s) sd[threadIdx.x] += sd[threadIdx.x + s];
        __syncthreads();
    }
    if (threadIdx.x == 0) g_chunksum[blockIdx.x] = sd[0];
}

__global__ void scan2_kernel(int nch) {
    __shared__ int sd[256];
    int t = threadIdx.x;
    int v = (t < nch) ? g_chunksum[t] : 0;
    sd[t] = v;
    __syncthreads();
    for (int off = 1; off < 256; off <<= 1) {
        int val = (t >= off) ? sd[t - off] : 0;
        __syncthreads();
        sd[t] += val;
        __syncthreads();
    }
    if (t < nch) g_chunkoff[t] = sd[t] - v;  // exclusive
}

__global__ void scan3_kernel(int N, int E) {
    __shared__ int sd[256];
    int t = threadIdx.x;
    int i = blockIdx.x * 256 + t;
    int v = (i < N) ? g_indeg[i] : 0;
    sd[t] = v;
    __syncthreads();
    for (int off = 1; off < 256; off <<= 1) {
        int val = (t >= off) ? sd[t - off] : 0;
        __syncthreads();
        sd[t] += val;
        __syncthreads();
    }
    if (i < N) {
        int rp = g_chunkoff[blockIdx.x] + sd[t] - v;
        g_rowptr[i] = rp;
        g_cursor[i] = rp;
    }
    if (i == 0) g_rowptr[N] = E;
}

// fill: onorm inline; also writes layer-0 pack (node_id[src], w)
__global__ void fill_kernel(const int* __restrict__ src,
                            const int* __restrict__ dst,
                            const int* __restrict__ node_ids, int E) {
    int e = blockIdx.x * blockDim.x + threadIdx.x;
    if (e < E) {
        int s = src[e];
        int d = dst[e];
        float wt = rsqrtf((float)g_outdeg[s]);
        int p = atomicAdd(&g_cursor[d], 1);
        int wb = __float_as_int(wt);
        g_epack[p] = make_int2(s, wb);
        g_epack0[p] = make_int2(node_ids[s], wb);
    }
}

// ---------------- CSR gather aggregation (BN fold), warp per dst --------
// Layer 0 reads the 175KB embedding table directly (L1-resident).
__global__ void gather_agg_kernel(const float* __restrict__ emb,
                                  int use_h, int N) {
    int gid = blockIdx.x * blockDim.x + threadIdx.x;
    int w = gid >> 5;
    int lane = gid & 31;
    if (w >= N) return;
    const float* buf = use_h ? g_h : emb;
    const int2* ep = use_h ? g_epack : g_epack0;
    int beg = g_rowptr[w];
    int end = g_rowptr[w + 1];
    float4 acc = make_float4(0.f, 0.f, 0.f, 0.f);
    float sw = 0.f;
#pragma unroll 8
    for (int j = beg; j < end; ++j) {
        int2 e = ep[j];
        float wt = __int_as_float(e.y);
        sw += wt;
        float4 v = ((const float4*)buf)[e.x * 32 + lane];
        acc.x += wt * v.x;
        acc.y += wt * v.y;
        acc.z += wt * v.z;
        acc.w += wt * v.w;
    }
    float inn = g_inorm[w];
    float4 sc = ((const float4*)g_scale)[lane];
    float4 sh = ((const float4*)g_shift)[lane];
    float4 o;
    o.x = inn * (sc.x * acc.x + sh.x * sw);
    o.y = inn * (sc.y * acc.y + sh.y * sw);
    o.z = inn * (sc.z * acc.z + sh.z * sw);
    o.w = inn * (sc.w * acc.w + sh.w * sw);
    ((float4*)g_agg)[w * 32 + lane] = o;
}

// ---------------- persistent tensor-core dual GEMM (bf16x3) --------------
// h = relu(agg @ W + b) + relu(BN(buf) @ Rw + rb); BN stats in registers;
// last finishing block computes next layer's scale/shift (fused stats).
#define SM_BWH  0
#define SM_BWL  32768
#define SM_BRH  65536
#define SM_BRL  98304
#define SM_A1H  131072
#define SM_A1L  147456
#define SM_A2H  163840
#define SM_A2L  180224
#define SM_BIAS 196608
#define SM_RB   197120
#define SM_SC   197632
#define SM_SH   198144
#define SM_CS   198656
#define SM_CQ   200704
#define TC_SMEM 202752
// Hs (64x64 float2, xor-swizzled) overlays SM_A1H..SM_A1H+32768

__global__ __launch_bounds__(256, 1)
void gemm_tc_kernel(const float* __restrict__ b, const float* __restrict__ rb,
                    const float* __restrict__ gamma,
                    const float* __restrict__ beta,
                    int l, int use_h, int N) {
    extern __shared__ char smc[];
    const int tid = threadIdx.x;
    const int lane = tid & 31;
    const int wid = tid >> 5;
    const bool br1 = (wid >= 4);
    const int wl = wid & 3;
    const int mtbase = (wl & 1) * 2;
    const int nh = wl >> 1;
    const float* buf = use_h ? g_h : g_x;

    unsigned* A1H = (unsigned*)(smc + SM_A1H);
    unsigned* A1L = (unsigned*)(smc + SM_A1L);
    unsigned* A2H = (unsigned*)(smc + SM_A2H);
    unsigned* A2L = (unsigned*)(smc + SM_A2L);
    float* bsm  = (float*)(smc + SM_BIAS);
    float* rbsm = (float*)(smc + SM_RB);
    float* scsm = (float*)(smc + SM_SC);
    float* shsm = (float*)(smc + SM_SH);
    float* scs4 = (float*)(smc + SM_CS);
    float* scq4 = (float*)(smc + SM_CQ);
    float2* Hp = (float2*)(smc + SM_A1H);

    // one-time: copy pre-permuted weight fragments (128 KB) + vectors
    {
        const uint4* src4 = (const uint4*)g_bfrag[l];
        uint4* dst4 = (uint4*)smc;
        for (int i = tid; i < 8192; i += 256) dst4[i] = src4[i];
        if (tid < 128) {
            bsm[tid] = b[tid];
            rbsm[tid] = rb[tid];
            scsm[tid] = g_scale[tid];
            shsm[tid] = g_shift[tid];
            scs4[tid] = 0.f; scs4[128 + tid] = 0.f;
            scs4[256 + tid] = 0.f; scs4[384 + tid] = 0.f;
            scq4[tid] = 0.f; scq4[128 + tid] = 0.f;
            scq4[256 + tid] = 0.f; scq4[384 + tid] = 0.f;
        }
    }

    const unsigned* Ah = br1 ? A2H : A1H;
    const unsigned* Al = br1 ? A2L : A1L;
    const unsigned* Bh = (const unsigned*)(smc + (br1 ? SM_BRH : SM_BWH));
    const unsigned* Bl = (const unsigned*)(smc + (br1 ? SM_BRL : SM_BWL));

    float cs[16], cq[16];
#pragma unroll
    for (int i = 0; i < 16; i++) { cs[i] = 0.f; cq[i] = 0.f; }

    const int nchunks = (N + 63) / 64;
    float4 pa[8], px[8];
    {   // prefetch first chunk
        int rb0 = blockIdx.x * 64;
#pragma unroll
        for (int it = 0; it < 8; ++it) {
            int idx = tid + it * 256;
            int row = rb0 + (idx >> 5);
            int q = idx & 31;
            float4 z = make_float4(0.f, 0.f, 0.f, 0.f);
            pa[it] = z; px[it] = z;
            if (row < N) {
                pa[it] = ((const float4*)g_agg)[row * 32 + q];
                px[it] = ((const float4*)buf)[row * 32 + q];
            }
        }
    }

    for (int chunk = blockIdx.x; chunk < nchunks; chunk += gridDim.x) {
        const int rowbase = chunk * 64;
        __syncthreads();  // previous chunk fully consumed (Hs/A frags)

        // ---- stage prefetched rows into fragments (A1=agg, A2=BN(buf)) --
#pragma unroll
        for (int it = 0; it < 8; ++it) {
            int idx = tid + it * 256;
            int r = idx >> 5, q = idx & 31;
            float4 va = pa[it];
            float4 vb = px[it];
            float4 sc = ((const float4*)scsm)[q];
            float4 sh = ((const float4*)shsm)[q];
            float4 vx;
            vx.x = vb.x * sc.x + sh.x;
            vx.y = vb.y * sc.y + sh.y;
            vx.z = vb.z * sc.z + sh.z;
            vx.w = vb.w * sc.w + sh.w;
            unsigned h1a, l1a, h1b, l1b, h2a, l2a, h2b, l2b;
            split2(va.x, va.y, h1a, l1a);
            split2(va.z, va.w, h1b, l1b);
            split2(vx.x, vx.y, h2a, l2a);
            split2(vx.z, vx.w, h2b, l2b);
            int p0 = 2 * q, p1 = 2 * q + 1;
            int mt = r >> 4, rr = r & 15;
            int kt = p0 >> 3;
            int pp0 = p0 & 7, pp1 = p1 & 7;
            int ln0 = (rr & 7) * 4 + (pp0 & 3);
            int ln1 = (rr & 7) * 4 + (pp1 & 3);
            int rg0 = (rr >> 3) + 2 * (pp0 >> 2);
            int rg1 = (rr >> 3) + 2 * (pp1 >> 2);
            int u0 = ((mt * 8 + kt) * 32 + ln0) * 4 + rg0;
            int u1 = ((mt * 8 + kt) * 32 + ln1) * 4 + rg1;
            A1H[u0] = h1a; A1L[u0] = l1a;
            A1H[u1] = h1b; A1L[u1] = l1b;
            A2H[u0] = h2a; A2L[u0] = l2a;
            A2H[u1] = h2b; A2L[u1] = l2b;
        }
        __syncthreads();

        // ---- issue prefetch for next chunk (hides L2 under mma) ----
        int nextbase = rowbase + gridDim.x * 64;
        if (nextbase < N) {
#pragma unroll
            for (int it = 0; it < 8; ++it) {
                int idx = tid + it * 256;
                int row = nextbase + (idx >> 5);
                int q = idx & 31;
                float4 z = make_float4(0.f, 0.f, 0.f, 0.f);
                pa[it] = z; px[it] = z;
                if (row < N) {
                    pa[it] = ((const float4*)g_agg)[row * 32 + q];
                    px[it] = ((const float4*)buf)[row * 32 + q];
                }
            }
        }

        // ---- mma mainloop ----
        float c[2][8][4];
#pragma unroll
        for (int i = 0; i < 2; i++)
#pragma unroll
            for (int j = 0; j < 8; j++)
#pragma unroll
                for (int q = 0; q < 4; q++) c[i][j][q] = 0.f;

#pragma unroll
        for (int kt = 0; kt < 8; ++kt) {
            uint4 ah0 = *(const uint4*)&Ah[(((mtbase + 0) * 8 + kt) * 32 + lane) * 4];
            uint4 ah1 = *(const uint4*)&Ah[(((mtbase + 1) * 8 + kt) * 32 + lane) * 4];
            uint4 al0 = *(const uint4*)&Al[(((mtbase + 0) * 8 + kt) * 32 + lane) * 4];
            uint4 al1 = *(const uint4*)&Al[(((mtbase + 1) * 8 + kt) * 32 + lane) * 4];
#pragma unroll
            for (int j = 0; j < 8; ++j) {
                int nt = nh * 8 + j;
                uint2 bh = *(const uint2*)&Bh[((kt * 16 + nt) * 32 + lane) * 2];
                uint2 bl = *(const uint2*)&Bl[((kt * 16 + nt) * 32 + lane) * 2];
                mma16816(c[0][j], ah0, bh);
                mma16816(c[0][j], ah0, bl);
                mma16816(c[0][j], al0, bh);
                mma16816(c[1][j], ah1, bh);
                mma16816(c[1][j], ah1, bl);
                mma16816(c[1][j], al1, bh);
            }
        }
        __syncthreads();  // all mma done before Hs overlays A1 frags

        // ---- branch 0: Hs = relu(agg@W + b)  (xor-swizzled smem) ----
        if (!br1) {
#pragma unroll
            for (int mt2 = 0; mt2 < 2; ++mt2)
#pragma unroll
                for (int j = 0; j < 8; ++j) {
                    int nt = nh * 8 + j;
                    int r0 = (mtbase + mt2) * 16 + (lane >> 2);
                    int cp = nt * 4 + (lane & 3);
                    float b0v = bsm[cp * 2], b1v = bsm[cp * 2 + 1];
                    float* cc = c[mt2][j];
                    Hp[r0 * 64 + (cp ^ (r0 & 7))] =
                        make_float2(fmaxf(cc[0] + b0v, 0.f),
                                    fmaxf(cc[1] + b1v, 0.f));
                    int r1 = r0 + 8;
                    Hp[r1 * 64 + (cp ^ (r1 & 7))] =
                        make_float2(fmaxf(cc[2] + b0v, 0.f),
                                    fmaxf(cc[3] + b1v, 0.f));
                }
        }
        __syncthreads();

        // ---- branch 1: h = relu(x@Rw + rb) + Hs; write + stats ----
        if (br1) {
#pragma unroll
            for (int mt2 = 0; mt2 < 2; ++mt2)
#pragma unroll
                for (int j = 0; j < 8; ++j) {
                    int nt = nh * 8 + j;
                    int r0 = (mtbase + mt2) * 16 + (lane >> 2);
                    int cp = nt * 4 + (lane & 3);
                    float rb0 = rbsm[cp * 2], rb1 = rbsm[cp * 2 + 1];
                    float* cc = c[mt2][j];
                    int row0 = rowbase + r0;
                    if (row0 < N) {
                        float2 hs = Hp[r0 * 64 + (cp ^ (r0 & 7))];
                        float v0 = fmaxf(cc[0] + rb0, 0.f) + hs.x;
                        float v1 = fmaxf(cc[1] + rb1, 0.f) + hs.y;
                        ((float2*)g_h)[row0 * 64 + cp] = make_float2(v0, v1);
                        cs[j * 2] += v0;     cq[j * 2] += v0 * v0;
                        cs[j * 2 + 1] += v1; cq[j * 2 + 1] += v1 * v1;
                    }
                    int r1 = r0 + 8;
                    int row1 = rowbase + r1;
                    if (row1 < N) {
                        float2 hs = Hp[r1 * 64 + (cp ^ (r1 & 7))];
                        float v0 = fmaxf(cc[2] + rb0, 0.f) + hs.x;
                        float v1 = fmaxf(cc[3] + rb1, 0.f) + hs.y;
                        ((float2*)g_h)[row1 * 64 + cp] = make_float2(v0, v1);
                        cs[j * 2] += v0;     cq[j * 2] += v0 * v0;
                        cs[j * 2 + 1] += v1; cq[j * 2 + 1] += v1 * v1;
                    }
                }
        }
    }

    // ---- flush BN stats ----
    __syncthreads();
    if (br1) {
#pragma unroll
        for (int i = 0; i < 16; i++) {
#pragma unroll
            for (int off = 4; off <= 16; off <<= 1) {
                cs[i] += __shfl_xor_sync(0xffffffffu, cs[i], off);
                cq[i] += __shfl_xor_sync(0xffffffffu, cq[i], off);
            }
        }
        if (lane < 4) {
#pragma unroll
            for (int j = 0; j < 8; j++) {
#pragma unroll
                for (int h2 = 0; h2 < 2; h2++) {
                    int col = nh * 64 + j * 8 + lane * 2 + h2;
                    atomicAdd(&scs4[wl * 128 + col], cs[j * 2 + h2]);
                    atomicAdd(&scq4[wl * 128 + col], cq[j * 2 + h2]);
                }
            }
        }
    }
    __syncthreads();
    if (tid < 128) {
        float s = scs4[tid] + scs4[128 + tid] + scs4[256 + tid] + scs4[384 + tid];
        float q = scq4[tid] + scq4[128 + tid] + scq4[256 + tid] + scq4[384 + tid];
        atomicAdd(&g_colsum[tid], s);
        atomicAdd(&g_colsq[tid], q);
    }

    // ---- fused stats: last finishing block computes scale/shift ----
    __threadfence();
    __shared__ unsigned s_last;
    if (tid == 0) s_last = (atomicAdd(&g_blkdone, 1u) == gridDim.x - 1u);
    __syncthreads();
    if (s_last) {
        if (tid < 128) {
            float invN = 1.0f / (float)N;
            float mu = g_colsum[tid] * invN;
            float var = g_colsq[tid] * invN - mu * mu;
            var = fmaxf(var, 0.f);
            float istd = rsqrtf(var + 1e-5f);
            float sc = gamma[tid] * istd;
            g_scale[tid] = sc;
            g_shift[tid] = beta[tid] - mu * sc;
            g_colsum[tid] = 0.f;
            g_colsq[tid] = 0.f;
        }
        if (tid == 0) g_blkdone = 0u;
    }
}

// ---------------- final normalize (last layer only) ----------------
__global__ void normalize_kernel(int N, float* __restrict__ out) {
    int total = N * 32;
    for (int idx = blockIdx.x * blockDim.x + threadIdx.x; idx < total;
         idx += gridDim.x * blockDim.x) {
        int c4 = idx & 31;
        float4 v = ((const float4*)g_h)[idx];
        float4 s = ((const float4*)g_scale)[c4];
        float4 sh = ((const float4*)g_shift)[c4];
        float4 r;
        r.x = v.x * s.x + sh.x;
        r.y = v.y * s.y + sh.y;
        r.z = v.z * s.z + sh.z;
        r.w = v.w * s.w + sh.w;
        ((float4*)out)[idx] = r;
    }
}

// ---------------- launch ----------------
extern "C" void kernel_launch(void* const* d_in, const int* in_sizes, int n_in,
                              void* d_out, int out_size) {
    const int*   node_ids = (const int*)d_in[0];
    const int*   src      = (const int*)d_in[1];
    const int*   dst      = (const int*)d_in[2];
    const float* emb      = (const float*)d_in[3];
    const float* Ws       = (const float*)d_in[4];
    const float* bs       = (const float*)d_in[5];
    const float* Rws      = (const float*)d_in[6];
    const float* Rbs      = (const float*)d_in[7];
    const float* gammas   = (const float*)d_in[8];
    const float* betas    = (const float*)d_in[9];

    const int N = in_sizes[0];
    const int E = in_sizes[1];
    const int L = in_sizes[4] / (D * D);
    const int nch = (N + 255) / 256;

    cudaFuncSetAttribute(gemm_tc_kernel,
                         cudaFuncAttributeMaxDynamicSharedMemorySize, TC_SMEM);

    // prep: init (zero deg + BN + wfrags + emb gather), deg, scans, fill
    int ithreads = N * 32;
    if (L * 32768 > ithreads) ithreads = L * 32768;
    init_kernel<<<(ithreads + 255) / 256, 256>>>(node_ids, emb, Ws, Rws, L, N);
    deg_kernel<<<(E + 255) / 256, 256>>>(src, dst, E);
    scan1_kernel<<<nch, 256>>>(N);
    scan2_kernel<<<1, 256>>>(nch);
    scan3_kernel<<<nch, 256>>>(N, E);
    fill_kernel<<<(E + 255) / 256, 256>>>(src, dst, node_ids, E);

    // layers: gather (BN-folded) -> persistent tc GEMM (+fused stats)
    for (int l = 0; l < L; ++l) {
        int use_h = (l > 0) ? 1 : 0;
        gather_agg_kernel<<<(N * 32 + 255) / 256, 256>>>(emb, use_h, N);
        gemm_tc_kernel<<<148, 256, TC_SMEM>>>(
            bs + l * D, Rbs + l * D, gammas + l * D, betas + l * D,
            l, use_h, N);
    }
    normalize_kernel<<<512, 256>>>(N, (float*)d_out);
}